// round 1
// baseline (speedup 1.0000x reference)
#include <cuda_runtime.h>
#include <math.h>

// Problem constants
#define BB   2
#define TT   2048
#define BT   4096        // B*T
#define DD   1024
#define HH   16
#define HD   64
#define NP   3
#define PP   256

// Scratch (allocation-free rule: __device__ globals)
__device__ float g_h   [BT * DD];        // rmsnorm1 output
__device__ float g_qkv [BT * 3 * DD];    // qkv projections
__device__ float g_attn[BT * DD];        // attention output
__device__ float g_x1  [BT * DD];        // x + attn @ o_w.T
__device__ float g_h2  [BT * DD];        // rmsnorm2 output

// ---------------------------------------------------------------------------
// rmsnorm + affine:  out = x * rsqrt(mean(x^2)+eps) * w * gamma + beta
// one block (256 thr) per row of 1024
// ---------------------------------------------------------------------------
__global__ void __launch_bounds__(256)
rmsnorm_kernel(const float* __restrict__ x, const float* __restrict__ w,
               const float* __restrict__ gamma, const float* __restrict__ beta,
               float* __restrict__ out)
{
    int m = blockIdx.x;
    int tid = threadIdx.x;
    const float* xr = x + (size_t)m * DD;

    float v[4];
    float s = 0.f;
#pragma unroll
    for (int u = 0; u < 4; u++) {
        v[u] = xr[tid + u * 256];
        s += v[u] * v[u];
    }
#pragma unroll
    for (int off = 16; off; off >>= 1) s += __shfl_xor_sync(0xffffffffu, s, off);

    __shared__ float red[8];
    int lane = tid & 31, wid = tid >> 5;
    if (lane == 0) red[wid] = s;
    __syncthreads();
    if (tid < 32) {
        float t = (tid < 8) ? red[tid] : 0.f;
#pragma unroll
        for (int off = 4; off; off >>= 1) t += __shfl_xor_sync(0xffffffffu, t, off);
        if (tid == 0) red[0] = t;
    }
    __syncthreads();

    float rms = rsqrtf(red[0] * (1.0f / (float)DD) + 1.1920929e-07f);
#pragma unroll
    for (int u = 0; u < 4; u++) {
        int d = tid + u * 256;
        out[(size_t)m * DD + d] = v[u] * rms * w[d] * gamma[d] + beta[d];
    }
}

// ---------------------------------------------------------------------------
// NT SGEMM: C[m,n] = sum_k A[m,k]*Bw[n,k]  (+ optional residual)
// BM=BN=64, BK=16, 256 threads, 4x4 per thread
// ---------------------------------------------------------------------------
template<bool RES>
__global__ void __launch_bounds__(256)
gemm_nt_kernel(const float* __restrict__ A, const float* __restrict__ Bw,
               const float* __restrict__ Res, float* __restrict__ C,
               int N, int K)
{
    __shared__ float As[16][68];
    __shared__ float Bs[16][68];

    int m0 = blockIdx.y * 64, n0 = blockIdx.x * 64;
    int tid = threadIdx.x;
    int tx = tid & 15, ty = tid >> 4;
    int lrow = tid >> 2;              // 0..63
    int lc4  = (tid & 3) << 2;        // 0,4,8,12

    const float* Aptr = A  + (size_t)(m0 + lrow) * K + lc4;
    const float* Bptr = Bw + (size_t)(n0 + lrow) * K + lc4;

    float acc[4][4] = {};

    for (int k0 = 0; k0 < K; k0 += 16) {
        float4 av = *(const float4*)(Aptr + k0);
        float4 bv = *(const float4*)(Bptr + k0);
        As[lc4 + 0][lrow] = av.x; As[lc4 + 1][lrow] = av.y;
        As[lc4 + 2][lrow] = av.z; As[lc4 + 3][lrow] = av.w;
        Bs[lc4 + 0][lrow] = bv.x; Bs[lc4 + 1][lrow] = bv.y;
        Bs[lc4 + 2][lrow] = bv.z; Bs[lc4 + 3][lrow] = bv.w;
        __syncthreads();

#pragma unroll
        for (int k = 0; k < 16; k++) {
            float4 a = *(const float4*)&As[k][ty * 4];
            float4 b = *(const float4*)&Bs[k][tx * 4];
            acc[0][0] += a.x * b.x; acc[0][1] += a.x * b.y;
            acc[0][2] += a.x * b.z; acc[0][3] += a.x * b.w;
            acc[1][0] += a.y * b.x; acc[1][1] += a.y * b.y;
            acc[1][2] += a.y * b.z; acc[1][3] += a.y * b.w;
            acc[2][0] += a.z * b.x; acc[2][1] += a.z * b.y;
            acc[2][2] += a.z * b.z; acc[2][3] += a.z * b.w;
            acc[3][0] += a.w * b.x; acc[3][1] += a.w * b.y;
            acc[3][2] += a.w * b.z; acc[3][3] += a.w * b.w;
        }
        __syncthreads();
    }

#pragma unroll
    for (int i = 0; i < 4; i++) {
#pragma unroll
        for (int j = 0; j < 4; j++) {
            size_t idx = (size_t)(m0 + ty * 4 + i) * N + (n0 + tx * 4 + j);
            C[idx] = RES ? (acc[i][j] + Res[idx]) : acc[i][j];
        }
    }
}

// ---------------------------------------------------------------------------
// Flash attention (fp32): per block = (b, h, 64-query tile).
// K/V tiles of 32 keys, online softmax, causal.
// qkv layout: row m = b*T + t, cols [0:D)=Q, [D:2D)=K, [2D:3D)=V, head h at h*64.
// ---------------------------------------------------------------------------
__global__ void __launch_bounds__(256)
flash_kernel(const float* __restrict__ qkv, float* __restrict__ out)
{
    int qt = blockIdx.x;   // 0..31
    int h  = blockIdx.y;   // 0..15
    int b  = blockIdx.z;   // 0..1

    __shared__ float Qs[64][68];
    __shared__ float Ks[32][68];
    __shared__ float Vs[32][68];
    __shared__ float Ps[32][68];   // P stored transposed: Ps[j][i]

    int tid = threadIdx.x;
    int tx = tid & 15, ty = tid >> 4;

    const size_t rs = 3 * DD;
    const int qcol = h * HD;

    // Load Q tile (64 x 64)
#pragma unroll
    for (int u = 0; u < 4; u++) {
        int e  = tid + u * 256;         // float4 index, 16 per row
        int r  = e >> 4;
        int c4 = (e & 15) << 2;
        float4 qv = *(const float4*)&qkv[(size_t)(b * TT + qt * 64 + r) * rs + qcol + c4];
        Qs[r][c4 + 0] = qv.x; Qs[r][c4 + 1] = qv.y;
        Qs[r][c4 + 2] = qv.z; Qs[r][c4 + 3] = qv.w;
    }

    float m_i[4], l_i[4];
    float o[4][4] = {};
#pragma unroll
    for (int i = 0; i < 4; i++) { m_i[i] = -INFINITY; l_i[i] = 0.f; }
    __syncthreads();

    const float scale = 0.125f;   // 1/sqrt(64)
    int ktiles = 2 * qt + 2;      // causal: key tiles 0 .. 2*qt+1

    for (int kt = 0; kt < ktiles; kt++) {
        // Load K and V tiles (32 x 64 each)
#pragma unroll
        for (int u = 0; u < 2; u++) {
            int e  = tid + u * 256;
            int r  = e >> 4;
            int c4 = (e & 15) << 2;
            size_t base = (size_t)(b * TT + kt * 32 + r) * rs + DD + qcol + c4;
            float4 kv = *(const float4*)&qkv[base];
            float4 vv = *(const float4*)&qkv[base + DD];
            Ks[r][c4 + 0] = kv.x; Ks[r][c4 + 1] = kv.y;
            Ks[r][c4 + 2] = kv.z; Ks[r][c4 + 3] = kv.w;
            Vs[r][c4 + 0] = vv.x; Vs[r][c4 + 1] = vv.y;
            Vs[r][c4 + 2] = vv.z; Vs[r][c4 + 3] = vv.w;
        }
        __syncthreads();

        // S = Q K^T  (4 rows x 2 cols per thread)
        float s[4][2] = {};
#pragma unroll
        for (int d4 = 0; d4 < 16; d4++) {
            float4 qv[4], kv[2];
#pragma unroll
            for (int i = 0; i < 4; i++) qv[i] = *(const float4*)&Qs[ty * 4 + i][d4 * 4];
#pragma unroll
            for (int j = 0; j < 2; j++) kv[j] = *(const float4*)&Ks[tx * 2 + j][d4 * 4];
#pragma unroll
            for (int i = 0; i < 4; i++)
#pragma unroll
                for (int j = 0; j < 2; j++)
                    s[i][j] += qv[i].x * kv[j].x + qv[i].y * kv[j].y
                             + qv[i].z * kv[j].z + qv[i].w * kv[j].w;
        }

        // Mask + online softmax (row groups = 16 lanes sharing ty)
#pragma unroll
        for (int i = 0; i < 4; i++) {
            int qg = qt * 64 + ty * 4 + i;
#pragma unroll
            for (int j = 0; j < 2; j++) {
                int kg = kt * 32 + tx * 2 + j;
                s[i][j] = (kg <= qg) ? s[i][j] * scale : -INFINITY;
            }
            float mt = fmaxf(s[i][0], s[i][1]);
#pragma unroll
            for (int off = 8; off; off >>= 1)
                mt = fmaxf(mt, __shfl_xor_sync(0xffffffffu, mt, off));
            float mnew  = fmaxf(m_i[i], mt);
            float alpha = expf(m_i[i] - mnew);
            float p0 = expf(s[i][0] - mnew);
            float p1 = expf(s[i][1] - mnew);
            float ls = p0 + p1;
#pragma unroll
            for (int off = 8; off; off >>= 1)
                ls += __shfl_xor_sync(0xffffffffu, ls, off);
            l_i[i] = l_i[i] * alpha + ls;
            m_i[i] = mnew;
            o[i][0] *= alpha; o[i][1] *= alpha; o[i][2] *= alpha; o[i][3] *= alpha;
            Ps[tx * 2 + 0][ty * 4 + i] = p0;
            Ps[tx * 2 + 1][ty * 4 + i] = p1;
        }
        __syncthreads();

        // O += P V   (thread owns rows ty*4.., d-cols tx*4..)
#pragma unroll
        for (int j = 0; j < 32; j++) {
            float4 pv = *(const float4*)&Ps[j][ty * 4];
            float4 vv = *(const float4*)&Vs[j][tx * 4];
            o[0][0] += pv.x * vv.x; o[0][1] += pv.x * vv.y; o[0][2] += pv.x * vv.z; o[0][3] += pv.x * vv.w;
            o[1][0] += pv.y * vv.x; o[1][1] += pv.y * vv.y; o[1][2] += pv.y * vv.z; o[1][3] += pv.y * vv.w;
            o[2][0] += pv.z * vv.x; o[2][1] += pv.z * vv.y; o[2][2] += pv.z * vv.z; o[2][3] += pv.z * vv.w;
            o[3][0] += pv.w * vv.x; o[3][1] += pv.w * vv.y; o[3][2] += pv.w * vv.z; o[3][3] += pv.w * vv.w;
        }
        __syncthreads();
    }

    // Normalize and write
#pragma unroll
    for (int i = 0; i < 4; i++) {
        int qg = qt * 64 + ty * 4 + i;
        float inv = 1.0f / l_i[i];
        size_t base = (size_t)(b * TT + qg) * DD + qcol + tx * 4;
        out[base + 0] = o[i][0] * inv;
        out[base + 1] = o[i][1] * inv;
        out[base + 2] = o[i][2] * inv;
        out[base + 3] = o[i][3] * inv;
    }
}

// ---------------------------------------------------------------------------
// Rotation FFN + SiLU + final residual combine.
// One block (256 thr) per row. r starts as h2; out = x1 + r - h2.
// pi/pj per pass are disjoint halves of a permutation -> in-place rotation
// by 256 threads is race-free.
// ---------------------------------------------------------------------------
__global__ void __launch_bounds__(256)
rotate_kernel(const float* __restrict__ h2, const float* __restrict__ x1,
              const float* __restrict__ angles, const float* __restrict__ gate,
              const float* __restrict__ bias, const int* __restrict__ pi,
              const int* __restrict__ pj, float* __restrict__ out)
{
    int m = blockIdx.x;
    int tid = threadIdx.x;
    __shared__ float sr[DD];

#pragma unroll
    for (int u = 0; u < 4; u++)
        sr[tid + u * 256] = h2[(size_t)m * DD + tid + u * 256];
    __syncthreads();

#pragma unroll
    for (int p = 0; p < NP; p++) {
        int ii = pi[p * PP + tid];
        int jj = pj[p * PP + tid];
        float a  = angles[p * PP + tid];
        float ca = cosf(a), sa = sinf(a);
        float hi = sr[ii], hj = sr[jj];
        sr[ii] = hi * ca - hj * sa;
        sr[jj] = hi * sa + hj * ca;
        __syncthreads();
#pragma unroll
        for (int u = 0; u < 4; u++) {
            int d = tid + u * 256;
            float v = sr[d] * gate[p * DD + d] + bias[p * DD + d];
            sr[d] = v / (1.f + expf(-v));   // silu
        }
        __syncthreads();
    }

#pragma unroll
    for (int u = 0; u < 4; u++) {
        int d = tid + u * 256;
        size_t idx = (size_t)m * DD + d;
        out[idx] = x1[idx] + sr[d] - h2[idx];
    }
}

// ---------------------------------------------------------------------------
// Launch
// ---------------------------------------------------------------------------
extern "C" void kernel_launch(void* const* d_in, const int* in_sizes, int n_in,
                              void* d_out, int out_size)
{
    const float* x      = (const float*)d_in[0];
    const float* gamma  = (const float*)d_in[1];
    const float* beta   = (const float*)d_in[2];
    const float* qkv_w  = (const float*)d_in[3];
    const float* o_w    = (const float*)d_in[4];
    const float* n1w    = (const float*)d_in[5];
    const float* n2w    = (const float*)d_in[6];
    const float* angles = (const float*)d_in[7];
    const float* gate   = (const float*)d_in[8];
    const float* bias   = (const float*)d_in[9];
    const int*   pi     = (const int*)d_in[10];
    const int*   pj     = (const int*)d_in[11];
    float* out = (float*)d_out;

    float *h, *qkvb, *attn, *x1, *h2;
    cudaGetSymbolAddress((void**)&h,    g_h);
    cudaGetSymbolAddress((void**)&qkvb, g_qkv);
    cudaGetSymbolAddress((void**)&attn, g_attn);
    cudaGetSymbolAddress((void**)&x1,   g_x1);
    cudaGetSymbolAddress((void**)&h2,   g_h2);

    // 1. h = rmsnorm(x)*gamma + beta
    rmsnorm_kernel<<<BT, 256>>>(x, n1w, gamma, beta, h);

    // 2. qkv = h @ qkv_w.T   [4096, 3072]
    gemm_nt_kernel<false><<<dim3(3 * DD / 64, BT / 64), 256>>>(h, qkv_w, nullptr, qkvb, 3 * DD, DD);

    // 3. causal attention -> attn [4096, 1024]
    flash_kernel<<<dim3(TT / 64, HH, BB), 256>>>(qkvb, attn);

    // 4. x1 = x + attn @ o_w.T
    gemm_nt_kernel<true><<<dim3(DD / 64, BT / 64), 256>>>(attn, o_w, x, x1, DD, DD);

    // 5. h2 = rmsnorm(x1)*gamma + beta
    rmsnorm_kernel<<<BT, 256>>>(x1, n2w, gamma, beta, h2);

    // 6. rotations + silu + residual -> out
    rotate_kernel<<<BT, 256>>>(h2, x1, angles, gate, bias, pi, pj, out);
}

// round 3
// speedup vs baseline: 2.9064x; 2.9064x over previous
#include <cuda_runtime.h>
#include <cuda_bf16.h>
#include <math.h>

// Problem constants
#define BB   2
#define TT   2048
#define BT   4096        // B*T
#define DD   1024
#define HH   16
#define HD   64
#define NP   3
#define PP   256

// Scratch (allocation-free rule: __device__ globals)
__device__ __nv_bfloat16 g_hb  [BT * DD];            // rmsnorm1 out, bf16
__device__ __nv_bfloat16 g_wb  [4 * DD * DD];        // [0:3D*D)=qkv_w bf16, [3D*D:4D*D)=o_w bf16
__device__ float         g_qkv [BT * 3 * DD];        // qkv projections (fp32)
__device__ __nv_bfloat16 g_attnb[BT * DD];           // attention out, bf16
__device__ float         g_x1  [BT * DD];            // x + attn @ o_w.T
__device__ float         g_h2  [BT * DD];            // rmsnorm2 out (fp32)

// ---------------------------------------------------------------------------
// fp32 -> bf16 conversion (weights), vectorized
// ---------------------------------------------------------------------------
__global__ void __launch_bounds__(256)
cvt_bf16_kernel(const float* __restrict__ a, const float* __restrict__ b,
                int na4, int nb4, __nv_bfloat16* __restrict__ out)
{
    int i = blockIdx.x * 256 + threadIdx.x;
    if (i < na4) {
        float4 v = ((const float4*)a)[i];
        __nv_bfloat162* o = (__nv_bfloat162*)(out) + i * 2;
        o[0] = __floats2bfloat162_rn(v.x, v.y);
        o[1] = __floats2bfloat162_rn(v.z, v.w);
    } else if (i < na4 + nb4) {
        int j = i - na4;
        float4 v = ((const float4*)b)[j];
        __nv_bfloat162* o = (__nv_bfloat162*)(out + (size_t)na4 * 4) + j * 2;
        o[0] = __floats2bfloat162_rn(v.x, v.y);
        o[1] = __floats2bfloat162_rn(v.z, v.w);
    }
}

// ---------------------------------------------------------------------------
// rmsnorm + affine. OUT = float or bf16.
// ---------------------------------------------------------------------------
template<typename OUT>
__global__ void __launch_bounds__(256)
rmsnorm_kernel(const float* __restrict__ x, const float* __restrict__ w,
               const float* __restrict__ gamma, const float* __restrict__ beta,
               OUT* __restrict__ out)
{
    int m = blockIdx.x;
    int tid = threadIdx.x;
    const float* xr = x + (size_t)m * DD;

    float v[4];
    float s = 0.f;
#pragma unroll
    for (int u = 0; u < 4; u++) {
        v[u] = xr[tid + u * 256];
        s += v[u] * v[u];
    }
#pragma unroll
    for (int off = 16; off; off >>= 1) s += __shfl_xor_sync(0xffffffffu, s, off);

    __shared__ float red[8];
    int lane = tid & 31, wid = tid >> 5;
    if (lane == 0) red[wid] = s;
    __syncthreads();
    if (tid < 32) {
        float t = (tid < 8) ? red[tid] : 0.f;
#pragma unroll
        for (int off = 4; off; off >>= 1) t += __shfl_xor_sync(0xffffffffu, t, off);
        if (tid == 0) red[0] = t;
    }
    __syncthreads();

    float rms = rsqrtf(red[0] * (1.0f / (float)DD) + 1.1920929e-07f);
#pragma unroll
    for (int u = 0; u < 4; u++) {
        int d = tid + u * 256;
        float r = v[u] * rms * w[d] * gamma[d] + beta[d];
        out[(size_t)m * DD + d] = (OUT)r;
    }
}

// ---------------------------------------------------------------------------
// bf16 tensor-core NT GEMM: C[m,n] = sum_k A[m,k]*Bw[n,k]  (+ optional residual)
// BM=128, BN=128, BK=32; 256 threads (8 warps, 4x2), warp tile 32x64.
// mma.sync.aligned.m16n8k16.row.col.f32.bf16.bf16.f32
// ---------------------------------------------------------------------------
#define SK 40   // padded smem stride (bf16 elems): conflict-free for frag loads

__device__ __forceinline__ void mma16816(float* c, const unsigned* a, const unsigned* b)
{
    asm volatile(
        "mma.sync.aligned.m16n8k16.row.col.f32.bf16.bf16.f32 "
        "{%0,%1,%2,%3}, {%4,%5,%6,%7}, {%8,%9}, {%0,%1,%2,%3};\n"
        : "+f"(c[0]), "+f"(c[1]), "+f"(c[2]), "+f"(c[3])
        : "r"(a[0]), "r"(a[1]), "r"(a[2]), "r"(a[3]), "r"(b[0]), "r"(b[1]));
}

template<bool RES>
__global__ void __launch_bounds__(256)
gemm_bf16_kernel(const __nv_bfloat16* __restrict__ A,
                 const __nv_bfloat16* __restrict__ Bw,
                 const float* __restrict__ Res, float* __restrict__ C,
                 int N, int K)
{
    __shared__ __nv_bfloat16 As[128 * SK];
    __shared__ __nv_bfloat16 Bs[128 * SK];

    const int m0 = blockIdx.y * 128, n0 = blockIdx.x * 128;
    const int tid  = threadIdx.x;
    const int warp = tid >> 5, lane = tid & 31;
    const int wm = warp >> 1, wn = warp & 1;          // 4 x 2 warp grid
    const int r  = lane >> 2;                          // 0..7
    const int cc = (lane & 3) * 2;                     // 0,2,4,6

    // global tile load: each thread loads 4 x (8 bf16) from A and from B.
    // tile is 128 rows x 32 cols = 512 chunks of 8; 256 thr -> 2 chunks each per mat? 
    // 128*32/8 = 512 chunks; 256 threads * 2 = 512.
    // chunk idx = tid + i*256 : row = idx>>2, c8 = (idx&3)*8
    float4 pa[2][2], pb[2][2];   // [chunk][two float4 halves]... we load as 2x float4 (8 floats? no)
    // A is bf16 in global: 8 bf16 = 16 bytes = one float4 load.
    const int ldrow0 = (tid * 2) >> 2;           // not used; compute inline

    // accumulators: 2 m-frags x 8 n-frags
    float acc[2][8][4];
#pragma unroll
    for (int i = 0; i < 2; i++)
#pragma unroll
        for (int j = 0; j < 8; j++)
#pragma unroll
            for (int q = 0; q < 4; q++) acc[i][j][q] = 0.f;

    // ---- load first tile ----
    uint4 ga[2], gb[2];
#pragma unroll
    for (int i = 0; i < 2; i++) {
        int idx = tid + i * 256;            // chunk of 8 bf16
        int row = idx >> 2, c8 = (idx & 3) * 8;
        ga[i] = *(const uint4*)&A [(size_t)(m0 + row) * K + c8];
        gb[i] = *(const uint4*)&Bw[(size_t)(n0 + row) * K + c8];
    }
#pragma unroll
    for (int i = 0; i < 2; i++) {
        int idx = tid + i * 256;
        int row = idx >> 2, c8 = (idx & 3) * 8;
        *(uint4*)&As[row * SK + c8] = ga[i];
        *(uint4*)&Bs[row * SK + c8] = gb[i];
    }
    __syncthreads();

    for (int k0 = 0; k0 < K; k0 += 32) {
        // prefetch next tile into registers
        bool more = (k0 + 32) < K;
        if (more) {
#pragma unroll
            for (int i = 0; i < 2; i++) {
                int idx = tid + i * 256;
                int row = idx >> 2, c8 = (idx & 3) * 8;
                ga[i] = *(const uint4*)&A [(size_t)(m0 + row) * K + k0 + 32 + c8];
                gb[i] = *(const uint4*)&Bw[(size_t)(n0 + row) * K + k0 + 32 + c8];
            }
        }

        // compute: 2 k-steps of 16
#pragma unroll
        for (int ks = 0; ks < 32; ks += 16) {
            unsigned afr[2][4], bfr[8][2];
#pragma unroll
            for (int mi = 0; mi < 2; mi++) {
                int mb = wm * 32 + mi * 16;
                afr[mi][0] = *(const unsigned*)&As[(mb + r    ) * SK + ks + cc    ];
                afr[mi][1] = *(const unsigned*)&As[(mb + r + 8) * SK + ks + cc    ];
                afr[mi][2] = *(const unsigned*)&As[(mb + r    ) * SK + ks + cc + 8];
                afr[mi][3] = *(const unsigned*)&As[(mb + r + 8) * SK + ks + cc + 8];
            }
#pragma unroll
            for (int ni = 0; ni < 8; ni++) {
                int nb = wn * 64 + ni * 8 + r;
                bfr[ni][0] = *(const unsigned*)&Bs[nb * SK + ks + cc    ];
                bfr[ni][1] = *(const unsigned*)&Bs[nb * SK + ks + cc + 8];
            }
#pragma unroll
            for (int mi = 0; mi < 2; mi++)
#pragma unroll
                for (int ni = 0; ni < 8; ni++)
                    mma16816(acc[mi][ni], afr[mi], bfr[ni]);
        }
        __syncthreads();

        if (more) {
#pragma unroll
            for (int i = 0; i < 2; i++) {
                int idx = tid + i * 256;
                int row = idx >> 2, c8 = (idx & 3) * 8;
                *(uint4*)&As[row * SK + c8] = ga[i];
                *(uint4*)&Bs[row * SK + c8] = gb[i];
            }
            __syncthreads();
        }
    }

    // ---- epilogue ----
#pragma unroll
    for (int mi = 0; mi < 2; mi++) {
#pragma unroll
        for (int ni = 0; ni < 8; ni++) {
            int col = n0 + wn * 64 + ni * 8 + cc;
            size_t i0 = (size_t)(m0 + wm * 32 + mi * 16 + r    ) * N + col;
            size_t i1 = (size_t)(m0 + wm * 32 + mi * 16 + r + 8) * N + col;
            float2 v0 = make_float2(acc[mi][ni][0], acc[mi][ni][1]);
            float2 v1 = make_float2(acc[mi][ni][2], acc[mi][ni][3]);
            if (RES) {
                float2 r0 = *(const float2*)&Res[i0];
                float2 r1 = *(const float2*)&Res[i1];
                v0.x += r0.x; v0.y += r0.y; v1.x += r1.x; v1.y += r1.y;
            }
            *(float2*)&C[i0] = v0;
            *(float2*)&C[i1] = v1;
        }
    }
}

// ---------------------------------------------------------------------------
// Flash attention (fp32 compute, bf16 output): block = (b, h, 64-query tile)
// ---------------------------------------------------------------------------
__global__ void __launch_bounds__(256)
flash_kernel(const float* __restrict__ qkv, __nv_bfloat16* __restrict__ out)
{
    int qt = blockIdx.x;
    int h  = blockIdx.y;
    int b  = blockIdx.z;

    __shared__ float Qs[64][68];
    __shared__ float Ks[32][68];
    __shared__ float Vs[32][68];
    __shared__ float Ps[32][68];

    int tid = threadIdx.x;
    int tx = tid & 15, ty = tid >> 4;

    const size_t rs = 3 * DD;
    const int qcol = h * HD;

#pragma unroll
    for (int u = 0; u < 4; u++) {
        int e  = tid + u * 256;
        int r  = e >> 4;
        int c4 = (e & 15) << 2;
        float4 qv = *(const float4*)&qkv[(size_t)(b * TT + qt * 64 + r) * rs + qcol + c4];
        Qs[r][c4 + 0] = qv.x; Qs[r][c4 + 1] = qv.y;
        Qs[r][c4 + 2] = qv.z; Qs[r][c4 + 3] = qv.w;
    }

    float m_i[4], l_i[4];
    float o[4][4] = {};
#pragma unroll
    for (int i = 0; i < 4; i++) { m_i[i] = -INFINITY; l_i[i] = 0.f; }
    __syncthreads();

    const float scale = 0.125f;
    int ktiles = 2 * qt + 2;

    for (int kt = 0; kt < ktiles; kt++) {
#pragma unroll
        for (int u = 0; u < 2; u++) {
            int e  = tid + u * 256;
            int r  = e >> 4;
            int c4 = (e & 15) << 2;
            size_t base = (size_t)(b * TT + kt * 32 + r) * rs + DD + qcol + c4;
            float4 kv = *(const float4*)&qkv[base];
            float4 vv = *(const float4*)&qkv[base + DD];
            Ks[r][c4 + 0] = kv.x; Ks[r][c4 + 1] = kv.y;
            Ks[r][c4 + 2] = kv.z; Ks[r][c4 + 3] = kv.w;
            Vs[r][c4 + 0] = vv.x; Vs[r][c4 + 1] = vv.y;
            Vs[r][c4 + 2] = vv.z; Vs[r][c4 + 3] = vv.w;
        }
        __syncthreads();

        float s[4][2] = {};
#pragma unroll
        for (int d4 = 0; d4 < 16; d4++) {
            float4 qv[4], kv[2];
#pragma unroll
            for (int i = 0; i < 4; i++) qv[i] = *(const float4*)&Qs[ty * 4 + i][d4 * 4];
#pragma unroll
            for (int j = 0; j < 2; j++) kv[j] = *(const float4*)&Ks[tx * 2 + j][d4 * 4];
#pragma unroll
            for (int i = 0; i < 4; i++)
#pragma unroll
                for (int j = 0; j < 2; j++)
                    s[i][j] += qv[i].x * kv[j].x + qv[i].y * kv[j].y
                             + qv[i].z * kv[j].z + qv[i].w * kv[j].w;
        }

#pragma unroll
        for (int i = 0; i < 4; i++) {
            int qg = qt * 64 + ty * 4 + i;
#pragma unroll
            for (int j = 0; j < 2; j++) {
                int kg = kt * 32 + tx * 2 + j;
                s[i][j] = (kg <= qg) ? s[i][j] * scale : -INFINITY;
            }
            float mt = fmaxf(s[i][0], s[i][1]);
#pragma unroll
            for (int off = 8; off; off >>= 1)
                mt = fmaxf(mt, __shfl_xor_sync(0xffffffffu, mt, off));
            float mnew  = fmaxf(m_i[i], mt);
            float alpha = expf(m_i[i] - mnew);
            float p0 = expf(s[i][0] - mnew);
            float p1 = expf(s[i][1] - mnew);
            float ls = p0 + p1;
#pragma unroll
            for (int off = 8; off; off >>= 1)
                ls += __shfl_xor_sync(0xffffffffu, ls, off);
            l_i[i] = l_i[i] * alpha + ls;
            m_i[i] = mnew;
            o[i][0] *= alpha; o[i][1] *= alpha; o[i][2] *= alpha; o[i][3] *= alpha;
            Ps[tx * 2 + 0][ty * 4 + i] = p0;
            Ps[tx * 2 + 1][ty * 4 + i] = p1;
        }
        __syncthreads();

#pragma unroll
        for (int j = 0; j < 32; j++) {
            float4 pv = *(const float4*)&Ps[j][ty * 4];
            float4 vv = *(const float4*)&Vs[j][tx * 4];
            o[0][0] += pv.x * vv.x; o[0][1] += pv.x * vv.y; o[0][2] += pv.x * vv.z; o[0][3] += pv.x * vv.w;
            o[1][0] += pv.y * vv.x; o[1][1] += pv.y * vv.y; o[1][2] += pv.y * vv.z; o[1][3] += pv.y * vv.w;
            o[2][0] += pv.z * vv.x; o[2][1] += pv.z * vv.y; o[2][2] += pv.z * vv.z; o[2][3] += pv.z * vv.w;
            o[3][0] += pv.w * vv.x; o[3][1] += pv.w * vv.y; o[3][2] += pv.w * vv.z; o[3][3] += pv.w * vv.w;
        }
        __syncthreads();
    }

#pragma unroll
    for (int i = 0; i < 4; i++) {
        int qg = qt * 64 + ty * 4 + i;
        float inv = 1.0f / l_i[i];
        size_t base = (size_t)(b * TT + qg) * DD + qcol + tx * 4;
        __nv_bfloat162* op = (__nv_bfloat162*)&out[base];
        op[0] = __floats2bfloat162_rn(o[i][0] * inv, o[i][1] * inv);
        op[1] = __floats2bfloat162_rn(o[i][2] * inv, o[i][3] * inv);
    }
}

// ---------------------------------------------------------------------------
// Rotation FFN + SiLU + final residual combine.
// ---------------------------------------------------------------------------
__global__ void __launch_bounds__(256)
rotate_kernel(const float* __restrict__ h2, const float* __restrict__ x1,
              const float* __restrict__ angles, const float* __restrict__ gate,
              const float* __restrict__ bias, const int* __restrict__ pi,
              const int* __restrict__ pj, float* __restrict__ out)
{
    int m = blockIdx.x;
    int tid = threadIdx.x;
    __shared__ float sr[DD];

#pragma unroll
    for (int u = 0; u < 4; u++)
        sr[tid + u * 256] = h2[(size_t)m * DD + tid + u * 256];
    __syncthreads();

#pragma unroll
    for (int p = 0; p < NP; p++) {
        int ii = pi[p * PP + tid];
        int jj = pj[p * PP + tid];
        float a  = angles[p * PP + tid];
        float ca = cosf(a), sa = sinf(a);
        float hi = sr[ii], hj = sr[jj];
        sr[ii] = hi * ca - hj * sa;
        sr[jj] = hi * sa + hj * ca;
        __syncthreads();
#pragma unroll
        for (int u = 0; u < 4; u++) {
            int d = tid + u * 256;
            float v = sr[d] * gate[p * DD + d] + bias[p * DD + d];
            sr[d] = v / (1.f + expf(-v));
        }
        __syncthreads();
    }

#pragma unroll
    for (int u = 0; u < 4; u++) {
        int d = tid + u * 256;
        size_t idx = (size_t)m * DD + d;
        out[idx] = x1[idx] + sr[d] - h2[idx];
    }
}

// ---------------------------------------------------------------------------
// Launch
// ---------------------------------------------------------------------------
extern "C" void kernel_launch(void* const* d_in, const int* in_sizes, int n_in,
                              void* d_out, int out_size)
{
    const float* x      = (const float*)d_in[0];
    const float* gamma  = (const float*)d_in[1];
    const float* beta   = (const float*)d_in[2];
    const float* qkv_w  = (const float*)d_in[3];
    const float* o_w    = (const float*)d_in[4];
    const float* n1w    = (const float*)d_in[5];
    const float* n2w    = (const float*)d_in[6];
    const float* angles = (const float*)d_in[7];
    const float* gate   = (const float*)d_in[8];
    const float* bias   = (const float*)d_in[9];
    const int*   pi     = (const int*)d_in[10];
    const int*   pj     = (const int*)d_in[11];
    float* out = (float*)d_out;

    __nv_bfloat16 *hb, *wb, *attnb;
    float *qkvb, *x1, *h2;
    cudaGetSymbolAddress((void**)&hb,    g_hb);
    cudaGetSymbolAddress((void**)&wb,    g_wb);
    cudaGetSymbolAddress((void**)&qkvb,  g_qkv);
    cudaGetSymbolAddress((void**)&attnb, g_attnb);
    cudaGetSymbolAddress((void**)&x1,    g_x1);
    cudaGetSymbolAddress((void**)&h2,    g_h2);

    // 0. convert weights to bf16: qkv_w (3D*D) then o_w (D*D)
    int na4 = 3 * DD * DD / 4, nb4 = DD * DD / 4;
    cvt_bf16_kernel<<<(na4 + nb4 + 255) / 256, 256>>>(qkv_w, o_w, na4, nb4, wb);

    // 1. h = rmsnorm(x)*gamma + beta  -> bf16
    rmsnorm_kernel<__nv_bfloat16><<<BT, 256>>>(x, n1w, gamma, beta, hb);

    // 2. qkv = h @ qkv_w.T   [4096, 3072]  (bf16 tensor core)
    gemm_bf16_kernel<false><<<dim3(3 * DD / 128, BT / 128), 256>>>(
        hb, wb, nullptr, qkvb, 3 * DD, DD);

    // 3. causal attention -> attnb [4096, 1024] bf16
    flash_kernel<<<dim3(TT / 64, HH, BB), 256>>>(qkvb, attnb);

    // 4. x1 = x + attn @ o_w.T  (bf16 tensor core + residual)
    gemm_bf16_kernel<true><<<dim3(DD / 128, BT / 128), 256>>>(
        attnb, wb + (size_t)3 * DD * DD, x, x1, DD, DD);

    // 5. h2 = rmsnorm(x1)*gamma + beta (fp32)
    rmsnorm_kernel<float><<<BT, 256>>>(x1, n2w, gamma, beta, h2);

    // 6. rotations + silu + residual -> out
    rotate_kernel<<<BT, 256>>>(h2, x1, angles, gate, bias, pi, pj, out);
}

// round 4
// speedup vs baseline: 9.3580x; 3.2198x over previous
#include <cuda_runtime.h>
#include <cuda_bf16.h>
#include <math.h>

// Problem constants
#define BB   2
#define TT   2048
#define BT   4096        // B*T
#define DD   1024
#define HH   16
#define HD   64
#define NP   3
#define PP   256

// Scratch (allocation-free rule: __device__ globals)
__device__ __nv_bfloat16 g_hb   [BT * DD];           // rmsnorm1 out, bf16
__device__ __nv_bfloat16 g_wb   [4 * DD * DD];       // bf16 weights: qkv_w | o_w
__device__ __nv_bfloat16 g_qkvb [BT * 3 * DD];       // qkv projections, bf16
__device__ __nv_bfloat16 g_attnb[BT * DD];           // attention out, bf16
__device__ float         g_x1   [BT * DD];           // x + attn @ o_w.T
__device__ float         g_h2   [BT * DD];           // rmsnorm2 out

// ---------------------------------------------------------------------------
// fp32 -> bf16 conversion (weights), vectorized
// ---------------------------------------------------------------------------
__global__ void __launch_bounds__(256)
cvt_bf16_kernel(const float* __restrict__ a, const float* __restrict__ b,
                int na4, int nb4, __nv_bfloat16* __restrict__ out)
{
    int i = blockIdx.x * 256 + threadIdx.x;
    if (i < na4) {
        float4 v = ((const float4*)a)[i];
        __nv_bfloat162* o = (__nv_bfloat162*)(out) + i * 2;
        o[0] = __floats2bfloat162_rn(v.x, v.y);
        o[1] = __floats2bfloat162_rn(v.z, v.w);
    } else if (i < na4 + nb4) {
        int j = i - na4;
        float4 v = ((const float4*)b)[j];
        __nv_bfloat162* o = (__nv_bfloat162*)(out + (size_t)na4 * 4) + j * 2;
        o[0] = __floats2bfloat162_rn(v.x, v.y);
        o[1] = __floats2bfloat162_rn(v.z, v.w);
    }
}

// ---------------------------------------------------------------------------
// rmsnorm + affine. OUT = float or bf16.
// ---------------------------------------------------------------------------
template<typename OUT>
__global__ void __launch_bounds__(256)
rmsnorm_kernel(const float* __restrict__ x, const float* __restrict__ w,
               const float* __restrict__ gamma, const float* __restrict__ beta,
               OUT* __restrict__ out)
{
    int m = blockIdx.x;
    int tid = threadIdx.x;
    const float* xr = x + (size_t)m * DD;

    float v[4];
    float s = 0.f;
#pragma unroll
    for (int u = 0; u < 4; u++) {
        v[u] = xr[tid + u * 256];
        s += v[u] * v[u];
    }
#pragma unroll
    for (int off = 16; off; off >>= 1) s += __shfl_xor_sync(0xffffffffu, s, off);

    __shared__ float red[8];
    int lane = tid & 31, wid = tid >> 5;
    if (lane == 0) red[wid] = s;
    __syncthreads();
    if (tid < 32) {
        float t = (tid < 8) ? red[tid] : 0.f;
#pragma unroll
        for (int off = 4; off; off >>= 1) t += __shfl_xor_sync(0xffffffffu, t, off);
        if (tid == 0) red[0] = t;
    }
    __syncthreads();

    float rms = rsqrtf(red[0] * (1.0f / (float)DD) + 1.1920929e-07f);
#pragma unroll
    for (int u = 0; u < 4; u++) {
        int d = tid + u * 256;
        float r = v[u] * rms * w[d] * gamma[d] + beta[d];
        out[(size_t)m * DD + d] = (OUT)r;
    }
}

// ---------------------------------------------------------------------------
// mma.m16n8k16 bf16 helper
// ---------------------------------------------------------------------------
__device__ __forceinline__ void mma16816(float* c, const unsigned* a, const unsigned* b)
{
    asm volatile(
        "mma.sync.aligned.m16n8k16.row.col.f32.bf16.bf16.f32 "
        "{%0,%1,%2,%3}, {%4,%5,%6,%7}, {%8,%9}, {%0,%1,%2,%3};\n"
        : "+f"(c[0]), "+f"(c[1]), "+f"(c[2]), "+f"(c[3])
        : "r"(a[0]), "r"(a[1]), "r"(a[2]), "r"(a[3]), "r"(b[0]), "r"(b[1]));
}

__device__ __forceinline__ void store2(float* p, float2 v) { *(float2*)p = v; }
__device__ __forceinline__ void store2(__nv_bfloat16* p, float2 v)
{ *(__nv_bfloat162*)p = __floats2bfloat162_rn(v.x, v.y); }

// ---------------------------------------------------------------------------
// bf16 tensor-core NT GEMM: C[m,n] = sum_k A[m,k]*Bw[n,k]  (+ optional residual)
// BM=128, BN=128, BK=32; 256 threads (8 warps, 4x2), warp tile 32x64.
// ---------------------------------------------------------------------------
#define SK 40

template<bool RES, typename OUT>
__global__ void __launch_bounds__(256)
gemm_bf16_kernel(const __nv_bfloat16* __restrict__ A,
                 const __nv_bfloat16* __restrict__ Bw,
                 const float* __restrict__ Res, OUT* __restrict__ C,
                 int N, int K)
{
    __shared__ __nv_bfloat16 As[128 * SK];
    __shared__ __nv_bfloat16 Bs[128 * SK];

    const int m0 = blockIdx.y * 128, n0 = blockIdx.x * 128;
    const int tid  = threadIdx.x;
    const int warp = tid >> 5, lane = tid & 31;
    const int wm = warp >> 1, wn = warp & 1;
    const int r  = lane >> 2;
    const int cc = (lane & 3) * 2;

    float acc[2][8][4];
#pragma unroll
    for (int i = 0; i < 2; i++)
#pragma unroll
        for (int j = 0; j < 8; j++)
#pragma unroll
            for (int q = 0; q < 4; q++) acc[i][j][q] = 0.f;

    uint4 ga[2], gb[2];
#pragma unroll
    for (int i = 0; i < 2; i++) {
        int idx = tid + i * 256;
        int row = idx >> 2, c8 = (idx & 3) * 8;
        ga[i] = *(const uint4*)&A [(size_t)(m0 + row) * K + c8];
        gb[i] = *(const uint4*)&Bw[(size_t)(n0 + row) * K + c8];
    }
#pragma unroll
    for (int i = 0; i < 2; i++) {
        int idx = tid + i * 256;
        int row = idx >> 2, c8 = (idx & 3) * 8;
        *(uint4*)&As[row * SK + c8] = ga[i];
        *(uint4*)&Bs[row * SK + c8] = gb[i];
    }
    __syncthreads();

    for (int k0 = 0; k0 < K; k0 += 32) {
        bool more = (k0 + 32) < K;
        if (more) {
#pragma unroll
            for (int i = 0; i < 2; i++) {
                int idx = tid + i * 256;
                int row = idx >> 2, c8 = (idx & 3) * 8;
                ga[i] = *(const uint4*)&A [(size_t)(m0 + row) * K + k0 + 32 + c8];
                gb[i] = *(const uint4*)&Bw[(size_t)(n0 + row) * K + k0 + 32 + c8];
            }
        }

#pragma unroll
        for (int ks = 0; ks < 32; ks += 16) {
            unsigned afr[2][4], bfr[8][2];
#pragma unroll
            for (int mi = 0; mi < 2; mi++) {
                int mb = wm * 32 + mi * 16;
                afr[mi][0] = *(const unsigned*)&As[(mb + r    ) * SK + ks + cc    ];
                afr[mi][1] = *(const unsigned*)&As[(mb + r + 8) * SK + ks + cc    ];
                afr[mi][2] = *(const unsigned*)&As[(mb + r    ) * SK + ks + cc + 8];
                afr[mi][3] = *(const unsigned*)&As[(mb + r + 8) * SK + ks + cc + 8];
            }
#pragma unroll
            for (int ni = 0; ni < 8; ni++) {
                int nb = wn * 64 + ni * 8 + r;
                bfr[ni][0] = *(const unsigned*)&Bs[nb * SK + ks + cc    ];
                bfr[ni][1] = *(const unsigned*)&Bs[nb * SK + ks + cc + 8];
            }
#pragma unroll
            for (int mi = 0; mi < 2; mi++)
#pragma unroll
                for (int ni = 0; ni < 8; ni++)
                    mma16816(acc[mi][ni], afr[mi], bfr[ni]);
        }
        __syncthreads();

        if (more) {
#pragma unroll
            for (int i = 0; i < 2; i++) {
                int idx = tid + i * 256;
                int row = idx >> 2, c8 = (idx & 3) * 8;
                *(uint4*)&As[row * SK + c8] = ga[i];
                *(uint4*)&Bs[row * SK + c8] = gb[i];
            }
            __syncthreads();
        }
    }

#pragma unroll
    for (int mi = 0; mi < 2; mi++) {
#pragma unroll
        for (int ni = 0; ni < 8; ni++) {
            int col = n0 + wn * 64 + ni * 8 + cc;
            size_t i0 = (size_t)(m0 + wm * 32 + mi * 16 + r    ) * N + col;
            size_t i1 = (size_t)(m0 + wm * 32 + mi * 16 + r + 8) * N + col;
            float2 v0 = make_float2(acc[mi][ni][0], acc[mi][ni][1]);
            float2 v1 = make_float2(acc[mi][ni][2], acc[mi][ni][3]);
            if (RES) {
                float2 r0 = *(const float2*)&Res[i0];
                float2 r1 = *(const float2*)&Res[i1];
                v0.x += r0.x; v0.y += r0.y; v1.x += r1.x; v1.y += r1.y;
            }
            store2(&C[i0], v0);
            store2(&C[i1], v1);
        }
    }
}

// ---------------------------------------------------------------------------
// Tensor-core flash attention (bf16 mma, fp32 softmax).
// Block = (64-query tile, head, batch); 128 threads (4 warps, 16 q-rows each).
// Key tiles of 64, causal tile skipping; diagonal tile masked.
// ---------------------------------------------------------------------------
#define VS 72    // smem stride (bf16) for 64-wide K/V tiles

__global__ void __launch_bounds__(128)
flash_mma_kernel(const __nv_bfloat16* __restrict__ qkv,
                 __nv_bfloat16* __restrict__ out)
{
    const int qt = blockIdx.x, h = blockIdx.y, b = blockIdx.z;

    __shared__ __nv_bfloat16 Ks[64 * VS];
    __shared__ __nv_bfloat16 Vsm[64 * VS];

    const int tid = threadIdx.x, warp = tid >> 5, lane = tid & 31;
    const int r = lane >> 2, cc = (lane & 3) * 2;
    const size_t rs = 3 * DD;
    const int qcol = h * HD;
    const int qrow0 = qt * 64 + warp * 16;   // warp's first query row (global t)

    // Q A-fragments, loaded straight from global (row-major, k = hd)
    unsigned qa[4][4];
    const __nv_bfloat16* qb = qkv + (size_t)(b * TT + qrow0) * rs + qcol;
#pragma unroll
    for (int ks = 0; ks < 4; ks++) {
        qa[ks][0] = *(const unsigned*)(qb + (size_t)(r    ) * rs + ks * 16 + cc    );
        qa[ks][1] = *(const unsigned*)(qb + (size_t)(r + 8) * rs + ks * 16 + cc    );
        qa[ks][2] = *(const unsigned*)(qb + (size_t)(r    ) * rs + ks * 16 + cc + 8);
        qa[ks][3] = *(const unsigned*)(qb + (size_t)(r + 8) * rs + ks * 16 + cc + 8);
    }

    float o[8][4];
#pragma unroll
    for (int i = 0; i < 8; i++)
#pragma unroll
        for (int q = 0; q < 4; q++) o[i][q] = 0.f;
    float m0 = -INFINITY, m1 = -INFINITY, l0 = 0.f, l1 = 0.f;

    const float scale = 0.125f;   // 1/sqrt(64)
    const int row0 = qrow0 + r, row1 = qrow0 + r + 8;   // this thread's rows

    for (int kt = 0; kt <= qt; kt++) {
        // ---- load K, V tiles (64 x 64 bf16 each) ----
#pragma unroll
        for (int i = 0; i < 4; i++) {
            int idx = tid + i * 128;            // 512 chunks of 8 bf16
            int row = idx >> 3, c8 = (idx & 7) * 8;
            size_t base = (size_t)(b * TT + kt * 64 + row) * rs + DD + qcol + c8;
            uint4 kv = *(const uint4*)&qkv[base];
            uint4 vv = *(const uint4*)&qkv[base + DD];
            *(uint4*)&Ks [row * VS + c8] = kv;
            *(uint4*)&Vsm[row * VS + c8] = vv;
        }
        __syncthreads();

        // ---- S = Q K^T (16 x 64 per warp) ----
        float s[8][4];
#pragma unroll
        for (int i = 0; i < 8; i++)
#pragma unroll
            for (int q = 0; q < 4; q++) s[i][q] = 0.f;
#pragma unroll
        for (int ni = 0; ni < 8; ni++) {
#pragma unroll
            for (int ks = 0; ks < 4; ks++) {
                unsigned kb[2];
                kb[0] = *(const unsigned*)&Ks[(ni * 8 + r) * VS + ks * 16 + cc    ];
                kb[1] = *(const unsigned*)&Ks[(ni * 8 + r) * VS + ks * 16 + cc + 8];
                mma16816(s[ni], qa[ks], kb);
            }
        }

        // ---- scale + causal mask ----
        if (kt == qt) {
#pragma unroll
            for (int ni = 0; ni < 8; ni++) {
                int c0 = kt * 64 + ni * 8 + cc, c1 = c0 + 1;
                s[ni][0] = (c0 <= row0) ? s[ni][0] * scale : -INFINITY;
                s[ni][1] = (c1 <= row0) ? s[ni][1] * scale : -INFINITY;
                s[ni][2] = (c0 <= row1) ? s[ni][2] * scale : -INFINITY;
                s[ni][3] = (c1 <= row1) ? s[ni][3] * scale : -INFINITY;
            }
        } else {
#pragma unroll
            for (int ni = 0; ni < 8; ni++)
#pragma unroll
                for (int q = 0; q < 4; q++) s[ni][q] *= scale;
        }

        // ---- online softmax (rows row0 / row1) ----
        float mx0 = -INFINITY, mx1 = -INFINITY;
#pragma unroll
        for (int ni = 0; ni < 8; ni++) {
            mx0 = fmaxf(mx0, fmaxf(s[ni][0], s[ni][1]));
            mx1 = fmaxf(mx1, fmaxf(s[ni][2], s[ni][3]));
        }
        mx0 = fmaxf(mx0, __shfl_xor_sync(0xffffffffu, mx0, 1));
        mx0 = fmaxf(mx0, __shfl_xor_sync(0xffffffffu, mx0, 2));
        mx1 = fmaxf(mx1, __shfl_xor_sync(0xffffffffu, mx1, 1));
        mx1 = fmaxf(mx1, __shfl_xor_sync(0xffffffffu, mx1, 2));

        float mn0 = fmaxf(m0, mx0), mn1 = fmaxf(m1, mx1);
        float a0 = __expf(m0 - mn0), a1 = __expf(m1 - mn1);
        m0 = mn0; m1 = mn1;

        float ls0 = 0.f, ls1 = 0.f;
#pragma unroll
        for (int ni = 0; ni < 8; ni++) {
            s[ni][0] = __expf(s[ni][0] - mn0);
            s[ni][1] = __expf(s[ni][1] - mn0);
            s[ni][2] = __expf(s[ni][2] - mn1);
            s[ni][3] = __expf(s[ni][3] - mn1);
            ls0 += s[ni][0] + s[ni][1];
            ls1 += s[ni][2] + s[ni][3];
        }
        ls0 += __shfl_xor_sync(0xffffffffu, ls0, 1);
        ls0 += __shfl_xor_sync(0xffffffffu, ls0, 2);
        ls1 += __shfl_xor_sync(0xffffffffu, ls1, 1);
        ls1 += __shfl_xor_sync(0xffffffffu, ls1, 2);
        l0 = l0 * a0 + ls0;
        l1 = l1 * a1 + ls1;

#pragma unroll
        for (int ni = 0; ni < 8; ni++) {
            o[ni][0] *= a0; o[ni][1] *= a0;
            o[ni][2] *= a1; o[ni][3] *= a1;
        }

        // ---- O += P V : pack P frags in-register, V B-frags via ldmatrix.trans ----
#pragma unroll
        for (int ks2 = 0; ks2 < 4; ks2++) {
            unsigned pa[4];
            pa[0] = ((unsigned)__bfloat16_as_ushort(__float2bfloat16(s[2*ks2  ][1])) << 16)
                  |  (unsigned)__bfloat16_as_ushort(__float2bfloat16(s[2*ks2  ][0]));
            pa[1] = ((unsigned)__bfloat16_as_ushort(__float2bfloat16(s[2*ks2  ][3])) << 16)
                  |  (unsigned)__bfloat16_as_ushort(__float2bfloat16(s[2*ks2  ][2]));
            pa[2] = ((unsigned)__bfloat16_as_ushort(__float2bfloat16(s[2*ks2+1][1])) << 16)
                  |  (unsigned)__bfloat16_as_ushort(__float2bfloat16(s[2*ks2+1][0]));
            pa[3] = ((unsigned)__bfloat16_as_ushort(__float2bfloat16(s[2*ks2+1][3])) << 16)
                  |  (unsigned)__bfloat16_as_ushort(__float2bfloat16(s[2*ks2+1][2]));

#pragma unroll
            for (int njp = 0; njp < 4; njp++) {
                const __nv_bfloat16* vp =
                    &Vsm[(ks2 * 16 + (lane & 15)) * VS + njp * 16 + ((lane >> 4) * 8)];
                unsigned addr = (unsigned)__cvta_generic_to_shared(vp);
                unsigned t0, t1, t2, t3;
                asm volatile(
                    "ldmatrix.sync.aligned.m8n8.x4.trans.shared.b16 "
                    "{%0,%1,%2,%3}, [%4];"
                    : "=r"(t0), "=r"(t1), "=r"(t2), "=r"(t3) : "r"(addr));
                unsigned vb0[2] = {t0, t1}, vb1[2] = {t2, t3};
                mma16816(o[2*njp    ], pa, vb0);
                mma16816(o[2*njp + 1], pa, vb1);
            }
        }
        __syncthreads();
    }

    // ---- normalize + write bf16 ----
    float inv0 = 1.0f / l0, inv1 = 1.0f / l1;
#pragma unroll
    for (int ni = 0; ni < 8; ni++) {
        size_t i0 = (size_t)(b * TT + row0) * DD + qcol + ni * 8 + cc;
        size_t i1 = (size_t)(b * TT + row1) * DD + qcol + ni * 8 + cc;
        *(__nv_bfloat162*)&out[i0] = __floats2bfloat162_rn(o[ni][0] * inv0, o[ni][1] * inv0);
        *(__nv_bfloat162*)&out[i1] = __floats2bfloat162_rn(o[ni][2] * inv1, o[ni][3] * inv1);
    }
}

// ---------------------------------------------------------------------------
// Rotation FFN + SiLU + final residual combine.
// ---------------------------------------------------------------------------
__global__ void __launch_bounds__(256)
rotate_kernel(const float* __restrict__ h2, const float* __restrict__ x1,
              const float* __restrict__ angles, const float* __restrict__ gate,
              const float* __restrict__ bias, const int* __restrict__ pi,
              const int* __restrict__ pj, float* __restrict__ out)
{
    int m = blockIdx.x;
    int tid = threadIdx.x;
    __shared__ float sr[DD];

#pragma unroll
    for (int u = 0; u < 4; u++)
        sr[tid + u * 256] = h2[(size_t)m * DD + tid + u * 256];
    __syncthreads();

#pragma unroll
    for (int p = 0; p < NP; p++) {
        int ii = pi[p * PP + tid];
        int jj = pj[p * PP + tid];
        float a  = angles[p * PP + tid];
        float ca = cosf(a), sa = sinf(a);
        float hi = sr[ii], hj = sr[jj];
        sr[ii] = hi * ca - hj * sa;
        sr[jj] = hi * sa + hj * ca;
        __syncthreads();
#pragma unroll
        for (int u = 0; u < 4; u++) {
            int d = tid + u * 256;
            float v = sr[d] * gate[p * DD + d] + bias[p * DD + d];
            sr[d] = v / (1.f + __expf(-v));
        }
        __syncthreads();
    }

#pragma unroll
    for (int u = 0; u < 4; u++) {
        int d = tid + u * 256;
        size_t idx = (size_t)m * DD + d;
        out[idx] = x1[idx] + sr[d] - h2[idx];
    }
}

// ---------------------------------------------------------------------------
// Launch
// ---------------------------------------------------------------------------
extern "C" void kernel_launch(void* const* d_in, const int* in_sizes, int n_in,
                              void* d_out, int out_size)
{
    const float* x      = (const float*)d_in[0];
    const float* gamma  = (const float*)d_in[1];
    const float* beta   = (const float*)d_in[2];
    const float* qkv_w  = (const float*)d_in[3];
    const float* o_w    = (const float*)d_in[4];
    const float* n1w    = (const float*)d_in[5];
    const float* n2w    = (const float*)d_in[6];
    const float* angles = (const float*)d_in[7];
    const float* gate   = (const float*)d_in[8];
    const float* bias   = (const float*)d_in[9];
    const int*   pi     = (const int*)d_in[10];
    const int*   pj     = (const int*)d_in[11];
    float* out = (float*)d_out;

    __nv_bfloat16 *hb, *wb, *qkvb, *attnb;
    float *x1, *h2;
    cudaGetSymbolAddress((void**)&hb,    g_hb);
    cudaGetSymbolAddress((void**)&wb,    g_wb);
    cudaGetSymbolAddress((void**)&qkvb,  g_qkvb);
    cudaGetSymbolAddress((void**)&attnb, g_attnb);
    cudaGetSymbolAddress((void**)&x1,    g_x1);
    cudaGetSymbolAddress((void**)&h2,    g_h2);

    // 0. weights -> bf16
    int na4 = 3 * DD * DD / 4, nb4 = DD * DD / 4;
    cvt_bf16_kernel<<<(na4 + nb4 + 255) / 256, 256>>>(qkv_w, o_w, na4, nb4, wb);

    // 1. h = rmsnorm(x)*gamma + beta  -> bf16
    rmsnorm_kernel<__nv_bfloat16><<<BT, 256>>>(x, n1w, gamma, beta, hb);

    // 2. qkv = h @ qkv_w.T  -> bf16  [4096, 3072]
    gemm_bf16_kernel<false, __nv_bfloat16><<<dim3(3 * DD / 128, BT / 128), 256>>>(
        hb, wb, nullptr, qkvb, 3 * DD, DD);

    // 3. causal attention (tensor core) -> attnb bf16
    flash_mma_kernel<<<dim3(TT / 64, HH, BB), 128>>>(qkvb, attnb);

    // 4. x1 = x + attn @ o_w.T (fp32 out + residual)
    gemm_bf16_kernel<true, float><<<dim3(DD / 128, BT / 128), 256>>>(
        attnb, wb + (size_t)3 * DD * DD, x, x1, DD, DD);

    // 5. h2 = rmsnorm(x1)*gamma + beta
    rmsnorm_kernel<float><<<BT, 256>>>(x1, n2w, gamma, beta, h2);

    // 6. rotations + silu + residual -> out
    rotate_kernel<<<BT, 256>>>(h2, x1, angles, gate, bias, pi, pj, out);
}

// round 5
// speedup vs baseline: 9.4525x; 1.0101x over previous
#include <cuda_runtime.h>
#include <cuda_bf16.h>
#include <math.h>

// Problem constants
#define BB   2
#define TT   2048
#define BT   4096        // B*T
#define DD   1024
#define HH   16
#define HD   64
#define NP   3
#define PP   256

// Scratch (allocation-free rule: __device__ globals)
__device__ __nv_bfloat16 g_hb   [BT * DD];           // rmsnorm1 out, bf16
__device__ __nv_bfloat16 g_wb   [4 * DD * DD];       // bf16 weights: qkv_w | o_w
__device__ __nv_bfloat16 g_qkvb [BT * 3 * DD];       // qkv projections, bf16
__device__ __nv_bfloat16 g_attnb[BT * DD];           // attention out, bf16
__device__ float         g_x1   [BT * DD];           // x + attn @ o_w.T

// ---------------------------------------------------------------------------
// cp.async helpers
// ---------------------------------------------------------------------------
__device__ __forceinline__ void cpasync16(void* s, const void* g)
{
    unsigned sa = (unsigned)__cvta_generic_to_shared(s);
    asm volatile("cp.async.cg.shared.global [%0], [%1], 16;" :: "r"(sa), "l"(g));
}
__device__ __forceinline__ void cp_commit()
{ asm volatile("cp.async.commit_group;"); }
template<int N> __device__ __forceinline__ void cp_wait()
{ asm volatile("cp.async.wait_group %0;" :: "n"(N)); }

// ---------------------------------------------------------------------------
// fp32 -> bf16 conversion (weights), vectorized
// ---------------------------------------------------------------------------
__global__ void __launch_bounds__(256)
cvt_bf16_kernel(const float* __restrict__ a, const float* __restrict__ b,
                int na4, int nb4, __nv_bfloat16* __restrict__ out)
{
    int i = blockIdx.x * 256 + threadIdx.x;
    if (i < na4) {
        float4 v = ((const float4*)a)[i];
        __nv_bfloat162* o = (__nv_bfloat162*)(out) + i * 2;
        o[0] = __floats2bfloat162_rn(v.x, v.y);
        o[1] = __floats2bfloat162_rn(v.z, v.w);
    } else if (i < na4 + nb4) {
        int j = i - na4;
        float4 v = ((const float4*)b)[j];
        __nv_bfloat162* o = (__nv_bfloat162*)(out + (size_t)na4 * 4) + j * 2;
        o[0] = __floats2bfloat162_rn(v.x, v.y);
        o[1] = __floats2bfloat162_rn(v.z, v.w);
    }
}

// ---------------------------------------------------------------------------
// rmsnorm + affine -> bf16 (feeds QKV GEMM)
// ---------------------------------------------------------------------------
__global__ void __launch_bounds__(256)
rmsnorm_kernel(const float* __restrict__ x, const float* __restrict__ w,
               const float* __restrict__ gamma, const float* __restrict__ beta,
               __nv_bfloat16* __restrict__ out)
{
    int m = blockIdx.x;
    int tid = threadIdx.x;
    const float* xr = x + (size_t)m * DD;

    float v[4];
    float s = 0.f;
#pragma unroll
    for (int u = 0; u < 4; u++) {
        v[u] = xr[tid + u * 256];
        s += v[u] * v[u];
    }
#pragma unroll
    for (int off = 16; off; off >>= 1) s += __shfl_xor_sync(0xffffffffu, s, off);

    __shared__ float red[8];
    int lane = tid & 31, wid = tid >> 5;
    if (lane == 0) red[wid] = s;
    __syncthreads();
    if (tid < 32) {
        float t = (tid < 8) ? red[tid] : 0.f;
#pragma unroll
        for (int off = 4; off; off >>= 1) t += __shfl_xor_sync(0xffffffffu, t, off);
        if (tid == 0) red[0] = t;
    }
    __syncthreads();

    float rms = rsqrtf(red[0] * (1.0f / (float)DD) + 1.1920929e-07f);
#pragma unroll
    for (int u = 0; u < 4; u++) {
        int d = tid + u * 256;
        float r = v[u] * rms * w[d] * gamma[d] + beta[d];
        out[(size_t)m * DD + d] = (__nv_bfloat16)r;
    }
}

// ---------------------------------------------------------------------------
// mma.m16n8k16 bf16 helper
// ---------------------------------------------------------------------------
__device__ __forceinline__ void mma16816(float* c, const unsigned* a, const unsigned* b)
{
    asm volatile(
        "mma.sync.aligned.m16n8k16.row.col.f32.bf16.bf16.f32 "
        "{%0,%1,%2,%3}, {%4,%5,%6,%7}, {%8,%9}, {%0,%1,%2,%3};\n"
        : "+f"(c[0]), "+f"(c[1]), "+f"(c[2]), "+f"(c[3])
        : "r"(a[0]), "r"(a[1]), "r"(a[2]), "r"(a[3]), "r"(b[0]), "r"(b[1]));
}

__device__ __forceinline__ void store2(float* p, float2 v) { *(float2*)p = v; }
__device__ __forceinline__ void store2(__nv_bfloat16* p, float2 v)
{ *(__nv_bfloat162*)p = __floats2bfloat162_rn(v.x, v.y); }

// ---------------------------------------------------------------------------
// bf16 tensor-core NT GEMM with cp.async 2-stage pipeline.
// BM=BN=128, BK=32; 256 threads (8 warps, 4x2), warp tile 32x64.
// ---------------------------------------------------------------------------
#define SK 40

template<bool RES, typename OUT>
__global__ void __launch_bounds__(256)
gemm_bf16_kernel(const __nv_bfloat16* __restrict__ A,
                 const __nv_bfloat16* __restrict__ Bw,
                 const float* __restrict__ Res, OUT* __restrict__ C,
                 int N, int K)
{
    __shared__ __nv_bfloat16 As[2][128 * SK];
    __shared__ __nv_bfloat16 Bs[2][128 * SK];

    const int m0 = blockIdx.y * 128, n0 = blockIdx.x * 128;
    const int tid  = threadIdx.x;
    const int warp = tid >> 5, lane = tid & 31;
    const int wm = warp >> 1, wn = warp & 1;
    const int r  = lane >> 2;
    const int cc = (lane & 3) * 2;

    // load coords: each thread 2 chunks of 8 bf16 per matrix
    const int row0l = tid >> 2,        c8l = (tid & 3) * 8;          // chunk tid
    const int row1l = (tid + 256) >> 2;                               // chunk tid+256

    float acc[2][8][4];
#pragma unroll
    for (int i = 0; i < 2; i++)
#pragma unroll
        for (int j = 0; j < 8; j++)
#pragma unroll
            for (int q = 0; q < 4; q++) acc[i][j][q] = 0.f;

    const int niter = K / 32;

    // prologue: stage 0
    {
        cpasync16(&As[0][row0l * SK + c8l], &A [(size_t)(m0 + row0l) * K + c8l]);
        cpasync16(&As[0][row1l * SK + c8l], &A [(size_t)(m0 + row1l) * K + c8l]);
        cpasync16(&Bs[0][row0l * SK + c8l], &Bw[(size_t)(n0 + row0l) * K + c8l]);
        cpasync16(&Bs[0][row1l * SK + c8l], &Bw[(size_t)(n0 + row1l) * K + c8l]);
        cp_commit();
    }

    for (int i = 0; i < niter; i++) {
        if (i + 1 < niter) {
            int st = (i + 1) & 1;
            int ko = (i + 1) * 32;
            cpasync16(&As[st][row0l * SK + c8l], &A [(size_t)(m0 + row0l) * K + ko + c8l]);
            cpasync16(&As[st][row1l * SK + c8l], &A [(size_t)(m0 + row1l) * K + ko + c8l]);
            cpasync16(&Bs[st][row0l * SK + c8l], &Bw[(size_t)(n0 + row0l) * K + ko + c8l]);
            cpasync16(&Bs[st][row1l * SK + c8l], &Bw[(size_t)(n0 + row1l) * K + ko + c8l]);
            cp_commit();
            cp_wait<1>();
        } else {
            cp_wait<0>();
        }
        __syncthreads();

        const __nv_bfloat16* Ac = As[i & 1];
        const __nv_bfloat16* Bc = Bs[i & 1];
#pragma unroll
        for (int ks = 0; ks < 32; ks += 16) {
            unsigned afr[2][4], bfr[8][2];
#pragma unroll
            for (int mi = 0; mi < 2; mi++) {
                int mb = wm * 32 + mi * 16;
                afr[mi][0] = *(const unsigned*)&Ac[(mb + r    ) * SK + ks + cc    ];
                afr[mi][1] = *(const unsigned*)&Ac[(mb + r + 8) * SK + ks + cc    ];
                afr[mi][2] = *(const unsigned*)&Ac[(mb + r    ) * SK + ks + cc + 8];
                afr[mi][3] = *(const unsigned*)&Ac[(mb + r + 8) * SK + ks + cc + 8];
            }
#pragma unroll
            for (int ni = 0; ni < 8; ni++) {
                int nb = wn * 64 + ni * 8 + r;
                bfr[ni][0] = *(const unsigned*)&Bc[nb * SK + ks + cc    ];
                bfr[ni][1] = *(const unsigned*)&Bc[nb * SK + ks + cc + 8];
            }
#pragma unroll
            for (int mi = 0; mi < 2; mi++)
#pragma unroll
                for (int ni = 0; ni < 8; ni++)
                    mma16816(acc[mi][ni], afr[mi], bfr[ni]);
        }
        __syncthreads();
    }

#pragma unroll
    for (int mi = 0; mi < 2; mi++) {
#pragma unroll
        for (int ni = 0; ni < 8; ni++) {
            int col = n0 + wn * 64 + ni * 8 + cc;
            size_t i0 = (size_t)(m0 + wm * 32 + mi * 16 + r    ) * N + col;
            size_t i1 = (size_t)(m0 + wm * 32 + mi * 16 + r + 8) * N + col;
            float2 v0 = make_float2(acc[mi][ni][0], acc[mi][ni][1]);
            float2 v1 = make_float2(acc[mi][ni][2], acc[mi][ni][3]);
            if (RES) {
                float2 r0 = *(const float2*)&Res[i0];
                float2 r1 = *(const float2*)&Res[i1];
                v0.x += r0.x; v0.y += r0.y; v1.x += r1.x; v1.y += r1.y;
            }
            store2(&C[i0], v0);
            store2(&C[i1], v1);
        }
    }
}

// ---------------------------------------------------------------------------
// Tensor-core flash attention: 128-query blocks, 8 warps, 64-key tiles.
// Reversed launch order so long (diagonal-heavy) blocks start first.
// ---------------------------------------------------------------------------
#define VS 72

__global__ void __launch_bounds__(256)
flash_mma_kernel(const __nv_bfloat16* __restrict__ qkv,
                 __nv_bfloat16* __restrict__ out)
{
    const int qt = gridDim.x - 1 - blockIdx.x;   // big blocks first
    const int h = blockIdx.y, b = blockIdx.z;

    __shared__ __nv_bfloat16 Ks[64 * VS];
    __shared__ __nv_bfloat16 Vsm[64 * VS];

    const int tid = threadIdx.x, warp = tid >> 5, lane = tid & 31;
    const int r = lane >> 2, cc = (lane & 3) * 2;
    const size_t rs = 3 * DD;
    const int qcol = h * HD;
    const int qrow0 = qt * 128 + warp * 16;

    // Q A-fragments from global
    unsigned qa[4][4];
    const __nv_bfloat16* qb = qkv + (size_t)(b * TT + qrow0) * rs + qcol;
#pragma unroll
    for (int ks = 0; ks < 4; ks++) {
        qa[ks][0] = *(const unsigned*)(qb + (size_t)(r    ) * rs + ks * 16 + cc    );
        qa[ks][1] = *(const unsigned*)(qb + (size_t)(r + 8) * rs + ks * 16 + cc    );
        qa[ks][2] = *(const unsigned*)(qb + (size_t)(r    ) * rs + ks * 16 + cc + 8);
        qa[ks][3] = *(const unsigned*)(qb + (size_t)(r + 8) * rs + ks * 16 + cc + 8);
    }

    float o[8][4];
#pragma unroll
    for (int i = 0; i < 8; i++)
#pragma unroll
        for (int q = 0; q < 4; q++) o[i][q] = 0.f;
    float m0 = -INFINITY, m1 = -INFINITY, l0 = 0.f, l1 = 0.f;

    const float scale = 0.125f;
    const int row0 = qrow0 + r, row1 = qrow0 + r + 8;
    const int ktiles = 2 * qt + 2;

    for (int kt = 0; kt < ktiles; kt++) {
        // load K, V tiles (64 x 64 bf16): 512 chunks each, 256 threads x 2
#pragma unroll
        for (int i = 0; i < 2; i++) {
            int idx = tid + i * 256;
            int row = idx >> 3, c8 = (idx & 7) * 8;
            size_t base = (size_t)(b * TT + kt * 64 + row) * rs + DD + qcol + c8;
            uint4 kv = *(const uint4*)&qkv[base];
            uint4 vv = *(const uint4*)&qkv[base + DD];
            *(uint4*)&Ks [row * VS + c8] = kv;
            *(uint4*)&Vsm[row * VS + c8] = vv;
        }
        __syncthreads();

        // S = Q K^T (16 x 64 per warp)
        float s[8][4];
#pragma unroll
        for (int i = 0; i < 8; i++)
#pragma unroll
            for (int q = 0; q < 4; q++) s[i][q] = 0.f;
#pragma unroll
        for (int ni = 0; ni < 8; ni++) {
#pragma unroll
            for (int ks = 0; ks < 4; ks++) {
                unsigned kb[2];
                kb[0] = *(const unsigned*)&Ks[(ni * 8 + r) * VS + ks * 16 + cc    ];
                kb[1] = *(const unsigned*)&Ks[(ni * 8 + r) * VS + ks * 16 + cc + 8];
                mma16816(s[ni], qa[ks], kb);
            }
        }

        // scale + causal mask (only diagonal band tiles need masking)
        if (kt >= 2 * qt) {
#pragma unroll
            for (int ni = 0; ni < 8; ni++) {
                int c0 = kt * 64 + ni * 8 + cc, c1 = c0 + 1;
                s[ni][0] = (c0 <= row0) ? s[ni][0] * scale : -INFINITY;
                s[ni][1] = (c1 <= row0) ? s[ni][1] * scale : -INFINITY;
                s[ni][2] = (c0 <= row1) ? s[ni][2] * scale : -INFINITY;
                s[ni][3] = (c1 <= row1) ? s[ni][3] * scale : -INFINITY;
            }
        } else {
#pragma unroll
            for (int ni = 0; ni < 8; ni++)
#pragma unroll
                for (int q = 0; q < 4; q++) s[ni][q] *= scale;
        }

        // online softmax
        float mx0 = -INFINITY, mx1 = -INFINITY;
#pragma unroll
        for (int ni = 0; ni < 8; ni++) {
            mx0 = fmaxf(mx0, fmaxf(s[ni][0], s[ni][1]));
            mx1 = fmaxf(mx1, fmaxf(s[ni][2], s[ni][3]));
        }
        mx0 = fmaxf(mx0, __shfl_xor_sync(0xffffffffu, mx0, 1));
        mx0 = fmaxf(mx0, __shfl_xor_sync(0xffffffffu, mx0, 2));
        mx1 = fmaxf(mx1, __shfl_xor_sync(0xffffffffu, mx1, 1));
        mx1 = fmaxf(mx1, __shfl_xor_sync(0xffffffffu, mx1, 2));

        float mn0 = fmaxf(m0, mx0), mn1 = fmaxf(m1, mx1);
        float a0 = __expf(m0 - mn0), a1 = __expf(m1 - mn1);
        m0 = mn0; m1 = mn1;

        float ls0 = 0.f, ls1 = 0.f;
#pragma unroll
        for (int ni = 0; ni < 8; ni++) {
            s[ni][0] = __expf(s[ni][0] - mn0);
            s[ni][1] = __expf(s[ni][1] - mn0);
            s[ni][2] = __expf(s[ni][2] - mn1);
            s[ni][3] = __expf(s[ni][3] - mn1);
            ls0 += s[ni][0] + s[ni][1];
            ls1 += s[ni][2] + s[ni][3];
        }
        ls0 += __shfl_xor_sync(0xffffffffu, ls0, 1);
        ls0 += __shfl_xor_sync(0xffffffffu, ls0, 2);
        ls1 += __shfl_xor_sync(0xffffffffu, ls1, 1);
        ls1 += __shfl_xor_sync(0xffffffffu, ls1, 2);
        l0 = l0 * a0 + ls0;
        l1 = l1 * a1 + ls1;

#pragma unroll
        for (int ni = 0; ni < 8; ni++) {
            o[ni][0] *= a0; o[ni][1] *= a0;
            o[ni][2] *= a1; o[ni][3] *= a1;
        }

        // O += P V
#pragma unroll
        for (int ks2 = 0; ks2 < 4; ks2++) {
            unsigned pa[4];
            pa[0] = ((unsigned)__bfloat16_as_ushort(__float2bfloat16(s[2*ks2  ][1])) << 16)
                  |  (unsigned)__bfloat16_as_ushort(__float2bfloat16(s[2*ks2  ][0]));
            pa[1] = ((unsigned)__bfloat16_as_ushort(__float2bfloat16(s[2*ks2  ][3])) << 16)
                  |  (unsigned)__bfloat16_as_ushort(__float2bfloat16(s[2*ks2  ][2]));
            pa[2] = ((unsigned)__bfloat16_as_ushort(__float2bfloat16(s[2*ks2+1][1])) << 16)
                  |  (unsigned)__bfloat16_as_ushort(__float2bfloat16(s[2*ks2+1][0]));
            pa[3] = ((unsigned)__bfloat16_as_ushort(__float2bfloat16(s[2*ks2+1][3])) << 16)
                  |  (unsigned)__bfloat16_as_ushort(__float2bfloat16(s[2*ks2+1][2]));

#pragma unroll
            for (int njp = 0; njp < 4; njp++) {
                const __nv_bfloat16* vp =
                    &Vsm[(ks2 * 16 + (lane & 15)) * VS + njp * 16 + ((lane >> 4) * 8)];
                unsigned addr = (unsigned)__cvta_generic_to_shared(vp);
                unsigned t0, t1, t2, t3;
                asm volatile(
                    "ldmatrix.sync.aligned.m8n8.x4.trans.shared.b16 "
                    "{%0,%1,%2,%3}, [%4];"
                    : "=r"(t0), "=r"(t1), "=r"(t2), "=r"(t3) : "r"(addr));
                unsigned vb0[2] = {t0, t1}, vb1[2] = {t2, t3};
                mma16816(o[2*njp    ], pa, vb0);
                mma16816(o[2*njp + 1], pa, vb1);
            }
        }
        __syncthreads();
    }

    float inv0 = 1.0f / l0, inv1 = 1.0f / l1;
#pragma unroll
    for (int ni = 0; ni < 8; ni++) {
        size_t i0 = (size_t)(b * TT + row0) * DD + qcol + ni * 8 + cc;
        size_t i1 = (size_t)(b * TT + row1) * DD + qcol + ni * 8 + cc;
        *(__nv_bfloat162*)&out[i0] = __floats2bfloat162_rn(o[ni][0] * inv0, o[ni][1] * inv0);
        *(__nv_bfloat162*)&out[i1] = __floats2bfloat162_rn(o[ni][2] * inv1, o[ni][3] * inv1);
    }
}

// ---------------------------------------------------------------------------
// Fused rmsnorm2 + rotation FFN + SiLU + final residual combine.
// out = x1 + rotate(h2) - h2, h2 = rmsnorm(x1)*gamma+beta (never hits HBM).
// ---------------------------------------------------------------------------
__global__ void __launch_bounds__(256)
rmsrot_kernel(const float* __restrict__ x1, const float* __restrict__ w,
              const float* __restrict__ gamma, const float* __restrict__ beta,
              const float* __restrict__ angles, const float* __restrict__ gate,
              const float* __restrict__ bias, const int* __restrict__ pi,
              const int* __restrict__ pj, float* __restrict__ out)
{
    int m = blockIdx.x;
    int tid = threadIdx.x;
    __shared__ float sr[DD];
    __shared__ float red[8];

    const float* xr = x1 + (size_t)m * DD;
    float v[4];
    float s = 0.f;
#pragma unroll
    for (int u = 0; u < 4; u++) {
        v[u] = xr[tid + u * 256];
        s += v[u] * v[u];
    }
#pragma unroll
    for (int off = 16; off; off >>= 1) s += __shfl_xor_sync(0xffffffffu, s, off);
    int lane = tid & 31, wid = tid >> 5;
    if (lane == 0) red[wid] = s;
    __syncthreads();
    if (tid < 32) {
        float t = (tid < 8) ? red[tid] : 0.f;
#pragma unroll
        for (int off = 4; off; off >>= 1) t += __shfl_xor_sync(0xffffffffu, t, off);
        if (tid == 0) red[0] = t;
    }
    __syncthreads();
    float rms = rsqrtf(red[0] * (1.0f / (float)DD) + 1.1920929e-07f);

    float h2r[4];
#pragma unroll
    for (int u = 0; u < 4; u++) {
        int d = tid + u * 256;
        h2r[u] = v[u] * rms * w[d] * gamma[d] + beta[d];
        sr[d] = h2r[u];
    }
    __syncthreads();

#pragma unroll
    for (int p = 0; p < NP; p++) {
        int ii = pi[p * PP + tid];
        int jj = pj[p * PP + tid];
        float a  = angles[p * PP + tid];
        float ca = cosf(a), sa = sinf(a);
        float hi = sr[ii], hj = sr[jj];
        sr[ii] = hi * ca - hj * sa;
        sr[jj] = hi * sa + hj * ca;
        __syncthreads();
#pragma unroll
        for (int u = 0; u < 4; u++) {
            int d = tid + u * 256;
            float t = sr[d] * gate[p * DD + d] + bias[p * DD + d];
            sr[d] = t / (1.f + __expf(-t));
        }
        __syncthreads();
    }

#pragma unroll
    for (int u = 0; u < 4; u++) {
        int d = tid + u * 256;
        out[(size_t)m * DD + d] = v[u] + sr[d] - h2r[u];
    }
}

// ---------------------------------------------------------------------------
// Launch
// ---------------------------------------------------------------------------
extern "C" void kernel_launch(void* const* d_in, const int* in_sizes, int n_in,
                              void* d_out, int out_size)
{
    const float* x      = (const float*)d_in[0];
    const float* gamma  = (const float*)d_in[1];
    const float* beta   = (const float*)d_in[2];
    const float* qkv_w  = (const float*)d_in[3];
    const float* o_w    = (const float*)d_in[4];
    const float* n1w    = (const float*)d_in[5];
    const float* n2w    = (const float*)d_in[6];
    const float* angles = (const float*)d_in[7];
    const float* gate   = (const float*)d_in[8];
    const float* bias   = (const float*)d_in[9];
    const int*   pi     = (const int*)d_in[10];
    const int*   pj     = (const int*)d_in[11];
    float* out = (float*)d_out;

    __nv_bfloat16 *hb, *wb, *qkvb, *attnb;
    float *x1;
    cudaGetSymbolAddress((void**)&hb,    g_hb);
    cudaGetSymbolAddress((void**)&wb,    g_wb);
    cudaGetSymbolAddress((void**)&qkvb,  g_qkvb);
    cudaGetSymbolAddress((void**)&attnb, g_attnb);
    cudaGetSymbolAddress((void**)&x1,    g_x1);

    // 0. weights -> bf16
    int na4 = 3 * DD * DD / 4, nb4 = DD * DD / 4;
    cvt_bf16_kernel<<<(na4 + nb4 + 255) / 256, 256>>>(qkv_w, o_w, na4, nb4, wb);

    // 1. h = rmsnorm(x)*gamma + beta  -> bf16
    rmsnorm_kernel<<<BT, 256>>>(x, n1w, gamma, beta, hb);

    // 2. qkv = h @ qkv_w.T  -> bf16  [4096, 3072]
    gemm_bf16_kernel<false, __nv_bfloat16><<<dim3(3 * DD / 128, BT / 128), 256>>>(
        hb, wb, nullptr, qkvb, 3 * DD, DD);

    // 3. causal attention (tensor core, 128-q blocks) -> attnb bf16
    flash_mma_kernel<<<dim3(TT / 128, HH, BB), 256>>>(qkvb, attnb);

    // 4. x1 = x + attn @ o_w.T
    gemm_bf16_kernel<true, float><<<dim3(DD / 128, BT / 128), 256>>>(
        attnb, wb + (size_t)3 * DD * DD, x, x1, DD, DD);

    // 5+6. fused rmsnorm2 + rotations + silu + residual -> out
    rmsrot_kernel<<<BT, 256>>>(x1, n2w, gamma, beta, angles, gate, bias, pi, pj, out);
}

// round 8
// speedup vs baseline: 10.1199x; 1.0706x over previous
#include <cuda_runtime.h>
#include <cuda_bf16.h>
#include <math.h>

// Problem constants
#define BB   2
#define TT   2048
#define BT   4096        // B*T
#define DD   1024
#define HH   16
#define HD   64
#define NP   3
#define PP   256

// Scratch (allocation-free rule: __device__ globals)
__device__ __nv_bfloat16 g_hb   [BT * DD];           // rmsnorm1 out, bf16
__device__ __nv_bfloat16 g_wb   [4 * DD * DD];       // bf16 weights: qkv_w | o_w
__device__ __nv_bfloat16 g_qkvb [BT * 3 * DD];       // qkv projections, bf16
__device__ __nv_bfloat16 g_attnb[BT * DD];           // attention out, bf16
__device__ float         g_x1   [BT * DD];           // x + attn @ o_w.T

// ---------------------------------------------------------------------------
// cp.async helpers
// ---------------------------------------------------------------------------
__device__ __forceinline__ void cpasync16(void* s, const void* g)
{
    unsigned sa = (unsigned)__cvta_generic_to_shared(s);
    asm volatile("cp.async.cg.shared.global [%0], [%1], 16;" :: "r"(sa), "l"(g));
}
__device__ __forceinline__ void cp_commit()
{ asm volatile("cp.async.commit_group;"); }
template<int N> __device__ __forceinline__ void cp_wait()
{ asm volatile("cp.async.wait_group %0;" :: "n"(N)); }

// ---------------------------------------------------------------------------
// fp32 -> bf16 conversion (weights), vectorized
// ---------------------------------------------------------------------------
__global__ void __launch_bounds__(256)
cvt_bf16_kernel(const float* __restrict__ a, const float* __restrict__ b,
                int na4, int nb4, __nv_bfloat16* __restrict__ out)
{
    int i = blockIdx.x * 256 + threadIdx.x;
    if (i < na4) {
        float4 v = ((const float4*)a)[i];
        __nv_bfloat162* o = (__nv_bfloat162*)(out) + i * 2;
        o[0] = __floats2bfloat162_rn(v.x, v.y);
        o[1] = __floats2bfloat162_rn(v.z, v.w);
    } else if (i < na4 + nb4) {
        int j = i - na4;
        float4 v = ((const float4*)b)[j];
        __nv_bfloat162* o = (__nv_bfloat162*)(out + (size_t)na4 * 4) + j * 2;
        o[0] = __floats2bfloat162_rn(v.x, v.y);
        o[1] = __floats2bfloat162_rn(v.z, v.w);
    }
}

// ---------------------------------------------------------------------------
// rmsnorm + affine -> bf16 (feeds QKV GEMM)
// ---------------------------------------------------------------------------
__global__ void __launch_bounds__(256)
rmsnorm_kernel(const float* __restrict__ x, const float* __restrict__ w,
               const float* __restrict__ gamma, const float* __restrict__ beta,
               __nv_bfloat16* __restrict__ out)
{
    int m = blockIdx.x;
    int tid = threadIdx.x;
    const float* xr = x + (size_t)m * DD;

    float v[4];
    float s = 0.f;
#pragma unroll
    for (int u = 0; u < 4; u++) {
        v[u] = xr[tid + u * 256];
        s += v[u] * v[u];
    }
#pragma unroll
    for (int off = 16; off; off >>= 1) s += __shfl_xor_sync(0xffffffffu, s, off);

    __shared__ float red[8];
    int lane = tid & 31, wid = tid >> 5;
    if (lane == 0) red[wid] = s;
    __syncthreads();
    if (tid < 32) {
        float t = (tid < 8) ? red[tid] : 0.f;
#pragma unroll
        for (int off = 4; off; off >>= 1) t += __shfl_xor_sync(0xffffffffu, t, off);
        if (tid == 0) red[0] = t;
    }
    __syncthreads();

    float rms = rsqrtf(red[0] * (1.0f / (float)DD) + 1.1920929e-07f);
#pragma unroll
    for (int u = 0; u < 4; u++) {
        int d = tid + u * 256;
        float r = v[u] * rms * w[d] * gamma[d] + beta[d];
        out[(size_t)m * DD + d] = (__nv_bfloat16)r;
    }
}

// ---------------------------------------------------------------------------
// mma.m16n8k16 bf16 helper
// ---------------------------------------------------------------------------
__device__ __forceinline__ void mma16816(float* c, const unsigned* a, const unsigned* b)
{
    asm volatile(
        "mma.sync.aligned.m16n8k16.row.col.f32.bf16.bf16.f32 "
        "{%0,%1,%2,%3}, {%4,%5,%6,%7}, {%8,%9}, {%0,%1,%2,%3};\n"
        : "+f"(c[0]), "+f"(c[1]), "+f"(c[2]), "+f"(c[3])
        : "r"(a[0]), "r"(a[1]), "r"(a[2]), "r"(a[3]), "r"(b[0]), "r"(b[1]));
}

__device__ __forceinline__ void store2(float* p, float2 v) { *(float2*)p = v; }
__device__ __forceinline__ void store2(__nv_bfloat16* p, float2 v)
{ *(__nv_bfloat162*)p = __floats2bfloat162_rn(v.x, v.y); }

// ---------------------------------------------------------------------------
// bf16 tensor-core NT GEMM, cp.async 2-stage, ONE barrier per BK-step.
// BM=BN=128, BK=32; 256 threads (8 warps, 4x2), warp tile 32x64.
// ---------------------------------------------------------------------------
#define SK 40

template<bool RES, typename OUT>
__global__ void __launch_bounds__(256)
gemm_bf16_kernel(const __nv_bfloat16* __restrict__ A,
                 const __nv_bfloat16* __restrict__ Bw,
                 const float* __restrict__ Res, OUT* __restrict__ C,
                 int N, int K)
{
    __shared__ __nv_bfloat16 As[2][128 * SK];
    __shared__ __nv_bfloat16 Bs[2][128 * SK];

    const int m0 = blockIdx.y * 128, n0 = blockIdx.x * 128;
    const int tid  = threadIdx.x;
    const int warp = tid >> 5, lane = tid & 31;
    const int wm = warp >> 1, wn = warp & 1;
    const int r  = lane >> 2;
    const int cc = (lane & 3) * 2;

    const int row0l = tid >> 2,        c8l = (tid & 3) * 8;
    const int row1l = (tid + 256) >> 2;

    float acc[2][8][4];
#pragma unroll
    for (int i = 0; i < 2; i++)
#pragma unroll
        for (int j = 0; j < 8; j++)
#pragma unroll
            for (int q = 0; q < 4; q++) acc[i][j][q] = 0.f;

    const int niter = K / 32;

    // prologue: stage 0
    cpasync16(&As[0][row0l * SK + c8l], &A [(size_t)(m0 + row0l) * K + c8l]);
    cpasync16(&As[0][row1l * SK + c8l], &A [(size_t)(m0 + row1l) * K + c8l]);
    cpasync16(&Bs[0][row0l * SK + c8l], &Bw[(size_t)(n0 + row0l) * K + c8l]);
    cpasync16(&Bs[0][row1l * SK + c8l], &Bw[(size_t)(n0 + row1l) * K + c8l]);
    cp_commit();

    for (int i = 0; i < niter; i++) {
        cp_wait<0>();
        __syncthreads();

        // prefetch next stage AFTER the barrier (prev compute on that buffer done)
        if (i + 1 < niter) {
            int st = (i + 1) & 1;
            int ko = (i + 1) * 32;
            cpasync16(&As[st][row0l * SK + c8l], &A [(size_t)(m0 + row0l) * K + ko + c8l]);
            cpasync16(&As[st][row1l * SK + c8l], &A [(size_t)(m0 + row1l) * K + ko + c8l]);
            cpasync16(&Bs[st][row0l * SK + c8l], &Bw[(size_t)(n0 + row0l) * K + ko + c8l]);
            cpasync16(&Bs[st][row1l * SK + c8l], &Bw[(size_t)(n0 + row1l) * K + ko + c8l]);
            cp_commit();
        }

        const __nv_bfloat16* Ac = As[i & 1];
        const __nv_bfloat16* Bc = Bs[i & 1];
#pragma unroll
        for (int ks = 0; ks < 32; ks += 16) {
            unsigned afr[2][4], bfr[8][2];
#pragma unroll
            for (int mi = 0; mi < 2; mi++) {
                int mb = wm * 32 + mi * 16;
                afr[mi][0] = *(const unsigned*)&Ac[(mb + r    ) * SK + ks + cc    ];
                afr[mi][1] = *(const unsigned*)&Ac[(mb + r + 8) * SK + ks + cc    ];
                afr[mi][2] = *(const unsigned*)&Ac[(mb + r    ) * SK + ks + cc + 8];
                afr[mi][3] = *(const unsigned*)&Ac[(mb + r + 8) * SK + ks + cc + 8];
            }
#pragma unroll
            for (int ni = 0; ni < 8; ni++) {
                int nb = wn * 64 + ni * 8 + r;
                bfr[ni][0] = *(const unsigned*)&Bc[nb * SK + ks + cc    ];
                bfr[ni][1] = *(const unsigned*)&Bc[nb * SK + ks + cc + 8];
            }
#pragma unroll
            for (int mi = 0; mi < 2; mi++)
#pragma unroll
                for (int ni = 0; ni < 8; ni++)
                    mma16816(acc[mi][ni], afr[mi], bfr[ni]);
        }
    }

    __syncthreads();   // protect smem before epilogue? not needed, but cheap ordering for exit
#pragma unroll
    for (int mi = 0; mi < 2; mi++) {
#pragma unroll
        for (int ni = 0; ni < 8; ni++) {
            int col = n0 + wn * 64 + ni * 8 + cc;
            size_t i0 = (size_t)(m0 + wm * 32 + mi * 16 + r    ) * N + col;
            size_t i1 = (size_t)(m0 + wm * 32 + mi * 16 + r + 8) * N + col;
            float2 v0 = make_float2(acc[mi][ni][0], acc[mi][ni][1]);
            float2 v1 = make_float2(acc[mi][ni][2], acc[mi][ni][3]);
            if (RES) {
                float2 r0 = *(const float2*)&Res[i0];
                float2 r1 = *(const float2*)&Res[i1];
                v0.x += r0.x; v0.y += r0.y; v1.x += r1.x; v1.y += r1.y;
            }
            store2(&C[i0], v0);
            store2(&C[i1], v1);
        }
    }
}

// ---------------------------------------------------------------------------
// Tensor-core flash attention: 64-query blocks, 4 warps, 64-key tiles,
// cp.async double-buffered K/V, one barrier per key tile.
// 1D grid ordered so the longest (high-qt) blocks launch first.
// ---------------------------------------------------------------------------
#define VS 72

__global__ void __launch_bounds__(128)
flash_mma_kernel(const __nv_bfloat16* __restrict__ qkv,
                 __nv_bfloat16* __restrict__ out)
{
    const int bi = blockIdx.x;
    const int qt = 31 - (bi >> 5);          // 32 q-tiles, big first
    const int h  = bi & 15;
    const int b  = (bi >> 4) & 1;

    __shared__ __nv_bfloat16 Ks [2][64 * VS];
    __shared__ __nv_bfloat16 Vsm[2][64 * VS];

    const int tid = threadIdx.x, warp = tid >> 5, lane = tid & 31;
    const int r = lane >> 2, cc = (lane & 3) * 2;
    const size_t rs = 3 * DD;
    const int qcol = h * HD;
    const int qrow0 = qt * 64 + warp * 16;

    // Q A-fragments straight from global
    unsigned qa[4][4];
    const __nv_bfloat16* qb = qkv + (size_t)(b * TT + qrow0) * rs + qcol;
#pragma unroll
    for (int ks = 0; ks < 4; ks++) {
        qa[ks][0] = *(const unsigned*)(qb + (size_t)(r    ) * rs + ks * 16 + cc    );
        qa[ks][1] = *(const unsigned*)(qb + (size_t)(r + 8) * rs + ks * 16 + cc    );
        qa[ks][2] = *(const unsigned*)(qb + (size_t)(r    ) * rs + ks * 16 + cc + 8);
        qa[ks][3] = *(const unsigned*)(qb + (size_t)(r + 8) * rs + ks * 16 + cc + 8);
    }

    float o[8][4];
#pragma unroll
    for (int i = 0; i < 8; i++)
#pragma unroll
        for (int q = 0; q < 4; q++) o[i][q] = 0.f;
    float m0 = -INFINITY, m1 = -INFINITY, l0 = 0.f, l1 = 0.f;

    const float scale = 0.125f;
    const int row0 = qrow0 + r, row1 = qrow0 + r + 8;

    // ---- prologue: async-load tile 0 ----
    {
        const size_t kbase = (size_t)(b * TT) * rs + DD + qcol;
#pragma unroll
        for (int i = 0; i < 4; i++) {
            int idx = tid + i * 128;
            int row = idx >> 3, c8 = (idx & 7) * 8;
            size_t src = kbase + (size_t)row * rs + c8;
            cpasync16(&Ks [0][row * VS + c8], &qkv[src]);
            cpasync16(&Vsm[0][row * VS + c8], &qkv[src + DD]);
        }
        cp_commit();
    }

    for (int kt = 0; kt <= qt; kt++) {
        cp_wait<0>();
        __syncthreads();

        // prefetch next K/V tile after barrier (prev compute on that buffer done)
        if (kt < qt) {
            int st = (kt + 1) & 1;
            const size_t kbase = (size_t)(b * TT + (kt + 1) * 64) * rs + DD + qcol;
#pragma unroll
            for (int i = 0; i < 4; i++) {
                int idx = tid + i * 128;
                int row = idx >> 3, c8 = (idx & 7) * 8;
                size_t src = kbase + (size_t)row * rs + c8;
                cpasync16(&Ks [st][row * VS + c8], &qkv[src]);
                cpasync16(&Vsm[st][row * VS + c8], &qkv[src + DD]);
            }
            cp_commit();
        }

        const __nv_bfloat16* Kc = Ks [kt & 1];
        const __nv_bfloat16* Vc = Vsm[kt & 1];

        // ---- S = Q K^T (16 x 64 per warp) ----
        float s[8][4];
#pragma unroll
        for (int i = 0; i < 8; i++)
#pragma unroll
            for (int q = 0; q < 4; q++) s[i][q] = 0.f;
#pragma unroll
        for (int ni = 0; ni < 8; ni++) {
#pragma unroll
            for (int ks = 0; ks < 4; ks++) {
                unsigned kb[2];
                kb[0] = *(const unsigned*)&Kc[(ni * 8 + r) * VS + ks * 16 + cc    ];
                kb[1] = *(const unsigned*)&Kc[(ni * 8 + r) * VS + ks * 16 + cc + 8];
                mma16816(s[ni], qa[ks], kb);
            }
        }

        // ---- scale + causal mask (diagonal tile only) ----
        if (kt == qt) {
#pragma unroll
            for (int ni = 0; ni < 8; ni++) {
                int c0 = kt * 64 + ni * 8 + cc, c1 = c0 + 1;
                s[ni][0] = (c0 <= row0) ? s[ni][0] * scale : -INFINITY;
                s[ni][1] = (c1 <= row0) ? s[ni][1] * scale : -INFINITY;
                s[ni][2] = (c0 <= row1) ? s[ni][2] * scale : -INFINITY;
                s[ni][3] = (c1 <= row1) ? s[ni][3] * scale : -INFINITY;
            }
        } else {
#pragma unroll
            for (int ni = 0; ni < 8; ni++)
#pragma unroll
                for (int q = 0; q < 4; q++) s[ni][q] *= scale;
        }

        // ---- online softmax ----
        float mx0 = -INFINITY, mx1 = -INFINITY;
#pragma unroll
        for (int ni = 0; ni < 8; ni++) {
            mx0 = fmaxf(mx0, fmaxf(s[ni][0], s[ni][1]));
            mx1 = fmaxf(mx1, fmaxf(s[ni][2], s[ni][3]));
        }
        mx0 = fmaxf(mx0, __shfl_xor_sync(0xffffffffu, mx0, 1));
        mx0 = fmaxf(mx0, __shfl_xor_sync(0xffffffffu, mx0, 2));
        mx1 = fmaxf(mx1, __shfl_xor_sync(0xffffffffu, mx1, 1));
        mx1 = fmaxf(mx1, __shfl_xor_sync(0xffffffffu, mx1, 2));

        float mn0 = fmaxf(m0, mx0), mn1 = fmaxf(m1, mx1);
        float a0 = __expf(m0 - mn0), a1 = __expf(m1 - mn1);
        m0 = mn0; m1 = mn1;

        float ls0 = 0.f, ls1 = 0.f;
#pragma unroll
        for (int ni = 0; ni < 8; ni++) {
            s[ni][0] = __expf(s[ni][0] - mn0);
            s[ni][1] = __expf(s[ni][1] - mn0);
            s[ni][2] = __expf(s[ni][2] - mn1);
            s[ni][3] = __expf(s[ni][3] - mn1);
            ls0 += s[ni][0] + s[ni][1];
            ls1 += s[ni][2] + s[ni][3];
        }
        ls0 += __shfl_xor_sync(0xffffffffu, ls0, 1);
        ls0 += __shfl_xor_sync(0xffffffffu, ls0, 2);
        ls1 += __shfl_xor_sync(0xffffffffu, ls1, 1);
        ls1 += __shfl_xor_sync(0xffffffffu, ls1, 2);
        l0 = l0 * a0 + ls0;
        l1 = l1 * a1 + ls1;

#pragma unroll
        for (int ni = 0; ni < 8; ni++) {
            o[ni][0] *= a0; o[ni][1] *= a0;
            o[ni][2] *= a1; o[ni][3] *= a1;
        }

        // ---- O += P V ----
#pragma unroll
        for (int ks2 = 0; ks2 < 4; ks2++) {
            unsigned pa[4];
            pa[0] = ((unsigned)__bfloat16_as_ushort(__float2bfloat16(s[2*ks2  ][1])) << 16)
                  |  (unsigned)__bfloat16_as_ushort(__float2bfloat16(s[2*ks2  ][0]));
            pa[1] = ((unsigned)__bfloat16_as_ushort(__float2bfloat16(s[2*ks2  ][3])) << 16)
                  |  (unsigned)__bfloat16_as_ushort(__float2bfloat16(s[2*ks2  ][2]));
            pa[2] = ((unsigned)__bfloat16_as_ushort(__float2bfloat16(s[2*ks2+1][1])) << 16)
                  |  (unsigned)__bfloat16_as_ushort(__float2bfloat16(s[2*ks2+1][0]));
            pa[3] = ((unsigned)__bfloat16_as_ushort(__float2bfloat16(s[2*ks2+1][3])) << 16)
                  |  (unsigned)__bfloat16_as_ushort(__float2bfloat16(s[2*ks2+1][2]));

#pragma unroll
            for (int njp = 0; njp < 4; njp++) {
                const __nv_bfloat16* vp =
                    &Vc[(ks2 * 16 + (lane & 15)) * VS + njp * 16 + ((lane >> 4) * 8)];
                unsigned addr = (unsigned)__cvta_generic_to_shared(vp);
                unsigned t0, t1, t2, t3;
                asm volatile(
                    "ldmatrix.sync.aligned.m8n8.x4.trans.shared.b16 "
                    "{%0,%1,%2,%3}, [%4];"
                    : "=r"(t0), "=r"(t1), "=r"(t2), "=r"(t3) : "r"(addr));
                unsigned vb0[2] = {t0, t1}, vb1[2] = {t2, t3};
                mma16816(o[2*njp    ], pa, vb0);
                mma16816(o[2*njp + 1], pa, vb1);
            }
        }
    }

    float inv0 = 1.0f / l0, inv1 = 1.0f / l1;
#pragma unroll
    for (int ni = 0; ni < 8; ni++) {
        size_t i0 = (size_t)(b * TT + row0) * DD + qcol + ni * 8 + cc;
        size_t i1 = (size_t)(b * TT + row1) * DD + qcol + ni * 8 + cc;
        *(__nv_bfloat162*)&out[i0] = __floats2bfloat162_rn(o[ni][0] * inv0, o[ni][1] * inv0);
        *(__nv_bfloat162*)&out[i1] = __floats2bfloat162_rn(o[ni][2] * inv1, o[ni][3] * inv1);
    }
}

// ---------------------------------------------------------------------------
// Fused rmsnorm2 + rotation FFN + SiLU + final residual combine.
// ---------------------------------------------------------------------------
__global__ void __launch_bounds__(256)
rmsrot_kernel(const float* __restrict__ x1, const float* __restrict__ w,
              const float* __restrict__ gamma, const float* __restrict__ beta,
              const float* __restrict__ angles, const float* __restrict__ gate,
              const float* __restrict__ bias, const int* __restrict__ pi,
              const int* __restrict__ pj, float* __restrict__ out)
{
    int m = blockIdx.x;
    int tid = threadIdx.x;
    __shared__ float sr[DD];
    __shared__ float red[8];

    const float* xr = x1 + (size_t)m * DD;
    float v[4];
    float s = 0.f;
#pragma unroll
    for (int u = 0; u < 4; u++) {
        v[u] = xr[tid + u * 256];
        s += v[u] * v[u];
    }
#pragma unroll
    for (int off = 16; off; off >>= 1) s += __shfl_xor_sync(0xffffffffu, s, off);
    int lane = tid & 31, wid = tid >> 5;
    if (lane == 0) red[wid] = s;
    __syncthreads();
    if (tid < 32) {
        float t = (tid < 8) ? red[tid] : 0.f;
#pragma unroll
        for (int off = 4; off; off >>= 1) t += __shfl_xor_sync(0xffffffffu, t, off);
        if (tid == 0) red[0] = t;
    }
    __syncthreads();
    float rms = rsqrtf(red[0] * (1.0f / (float)DD) + 1.1920929e-07f);

    float h2r[4];
#pragma unroll
    for (int u = 0; u < 4; u++) {
        int d = tid + u * 256;
        h2r[u] = v[u] * rms * w[d] * gamma[d] + beta[d];
        sr[d] = h2r[u];
    }
    __syncthreads();

#pragma unroll
    for (int p = 0; p < NP; p++) {
        int ii = pi[p * PP + tid];
        int jj = pj[p * PP + tid];
        float a  = angles[p * PP + tid];
        float ca = cosf(a), sa = sinf(a);
        float hi = sr[ii], hj = sr[jj];
        sr[ii] = hi * ca - hj * sa;
        sr[jj] = hi * sa + hj * ca;
        __syncthreads();
#pragma unroll
        for (int u = 0; u < 4; u++) {
            int d = tid + u * 256;
            float t = sr[d] * gate[p * DD + d] + bias[p * DD + d];
            sr[d] = t / (1.f + __expf(-t));
        }
        __syncthreads();
    }

#pragma unroll
    for (int u = 0; u < 4; u++) {
        int d = tid + u * 256;
        out[(size_t)m * DD + d] = v[u] + sr[d] - h2r[u];
    }
}

// ---------------------------------------------------------------------------
// Launch
// ---------------------------------------------------------------------------
extern "C" void kernel_launch(void* const* d_in, const int* in_sizes, int n_in,
                              void* d_out, int out_size)
{
    const float* x      = (const float*)d_in[0];
    const float* gamma  = (const float*)d_in[1];
    const float* beta   = (const float*)d_in[2];
    const float* qkv_w  = (const float*)d_in[3];
    const float* o_w    = (const float*)d_in[4];
    const float* n1w    = (const float*)d_in[5];
    const float* n2w    = (const float*)d_in[6];
    const float* angles = (const float*)d_in[7];
    const float* gate   = (const float*)d_in[8];
    const float* bias   = (const float*)d_in[9];
    const int*   pi     = (const int*)d_in[10];
    const int*   pj     = (const int*)d_in[11];
    float* out = (float*)d_out;

    __nv_bfloat16 *hb, *wb, *qkvb, *attnb;
    float *x1;
    cudaGetSymbolAddress((void**)&hb,    g_hb);
    cudaGetSymbolAddress((void**)&wb,    g_wb);
    cudaGetSymbolAddress((void**)&qkvb,  g_qkvb);
    cudaGetSymbolAddress((void**)&attnb, g_attnb);
    cudaGetSymbolAddress((void**)&x1,    g_x1);

    // 0. weights -> bf16
    int na4 = 3 * DD * DD / 4, nb4 = DD * DD / 4;
    cvt_bf16_kernel<<<(na4 + nb4 + 255) / 256, 256>>>(qkv_w, o_w, na4, nb4, wb);

    // 1. h = rmsnorm(x)*gamma + beta  -> bf16
    rmsnorm_kernel<<<BT, 256>>>(x, n1w, gamma, beta, hb);

    // 2. qkv = h @ qkv_w.T  -> bf16  [4096, 3072]
    gemm_bf16_kernel<false, __nv_bfloat16><<<dim3(3 * DD / 128, BT / 128), 256>>>(
        hb, wb, nullptr, qkvb, 3 * DD, DD);

    // 3. causal attention (tensor core, 64-q blocks, async pipeline)
    flash_mma_kernel<<<1024, 128>>>(qkvb, attnb);

    // 4. x1 = x + attn @ o_w.T
    gemm_bf16_kernel<true, float><<<dim3(DD / 128, BT / 128), 256>>>(
        attnb, wb + (size_t)3 * DD * DD, x, x1, DD, DD);

    // 5+6. fused rmsnorm2 + rotations + silu + residual -> out
    rmsrot_kernel<<<BT, 256>>>(x1, n2w, gamma, beta, angles, gate, bias, pi, pj, out);
}

// round 9
// speedup vs baseline: 10.4714x; 1.0347x over previous
#include <cuda_runtime.h>
#include <cuda_bf16.h>
#include <math.h>

// Problem constants
#define BB   2
#define TT   2048
#define BT   4096        // B*T
#define DD   1024
#define HH   16
#define HD   64
#define NP   3
#define PP   256

// Scratch (allocation-free rule: __device__ globals)
__device__ __nv_bfloat16 g_hb   [BT * DD];           // rmsnorm1 out, bf16
__device__ __nv_bfloat16 g_wb   [4 * DD * DD];       // bf16 weights: qkv_w | o_w
__device__ __nv_bfloat16 g_qkvb [BT * 3 * DD];       // qkv projections, bf16
__device__ __nv_bfloat16 g_attnb[BT * DD];           // attention out, bf16
__device__ float         g_x1   [BT * DD];           // x + attn @ o_w.T

// ---------------------------------------------------------------------------
// cp.async helpers
// ---------------------------------------------------------------------------
__device__ __forceinline__ void cpasync16(void* s, const void* g)
{
    unsigned sa = (unsigned)__cvta_generic_to_shared(s);
    asm volatile("cp.async.cg.shared.global [%0], [%1], 16;" :: "r"(sa), "l"(g));
}
__device__ __forceinline__ void cp_commit()
{ asm volatile("cp.async.commit_group;"); }
template<int N> __device__ __forceinline__ void cp_wait()
{ asm volatile("cp.async.wait_group %0;" :: "n"(N)); }

// ---------------------------------------------------------------------------
// Fused prep: blocks [0, BT) do rmsnorm1 -> bf16; blocks [BT, BT+4096) convert
// weights fp32 -> bf16 (qkv_w then o_w).
// ---------------------------------------------------------------------------
__global__ void __launch_bounds__(256)
prep_kernel(const float* __restrict__ x, const float* __restrict__ w,
            const float* __restrict__ gamma, const float* __restrict__ beta,
            __nv_bfloat16* __restrict__ hb,
            const float* __restrict__ qkvw, const float* __restrict__ ow,
            __nv_bfloat16* __restrict__ wb)
{
    int tid = threadIdx.x;
    if (blockIdx.x >= BT) {
        // weight conversion: 1M float4 chunks total
        const int na4 = 3 * DD * DD / 4, nb4 = DD * DD / 4;
        int i = (blockIdx.x - BT) * 256 + tid;
        if (i < na4) {
            float4 v = ((const float4*)qkvw)[i];
            __nv_bfloat162* o = (__nv_bfloat162*)(wb) + i * 2;
            o[0] = __floats2bfloat162_rn(v.x, v.y);
            o[1] = __floats2bfloat162_rn(v.z, v.w);
        } else if (i < na4 + nb4) {
            int j = i - na4;
            float4 v = ((const float4*)ow)[j];
            __nv_bfloat162* o = (__nv_bfloat162*)(wb + (size_t)na4 * 4) + j * 2;
            o[0] = __floats2bfloat162_rn(v.x, v.y);
            o[1] = __floats2bfloat162_rn(v.z, v.w);
        }
        return;
    }

    int m = blockIdx.x;
    const float* xr = x + (size_t)m * DD;

    float v[4];
    float s = 0.f;
#pragma unroll
    for (int u = 0; u < 4; u++) {
        v[u] = xr[tid + u * 256];
        s += v[u] * v[u];
    }
#pragma unroll
    for (int off = 16; off; off >>= 1) s += __shfl_xor_sync(0xffffffffu, s, off);

    __shared__ float red[8];
    int lane = tid & 31, wid = tid >> 5;
    if (lane == 0) red[wid] = s;
    __syncthreads();
    if (tid < 32) {
        float t = (tid < 8) ? red[tid] : 0.f;
#pragma unroll
        for (int off = 4; off; off >>= 1) t += __shfl_xor_sync(0xffffffffu, t, off);
        if (tid == 0) red[0] = t;
    }
    __syncthreads();

    float rms = rsqrtf(red[0] * (1.0f / (float)DD) + 1.1920929e-07f);
#pragma unroll
    for (int u = 0; u < 4; u++) {
        int d = tid + u * 256;
        float r = v[u] * rms * w[d] * gamma[d] + beta[d];
        hb[(size_t)m * DD + d] = (__nv_bfloat16)r;
    }
}

// ---------------------------------------------------------------------------
// mma.m16n8k16 bf16 helper
// ---------------------------------------------------------------------------
__device__ __forceinline__ void mma16816(float* c, const unsigned* a, const unsigned* b)
{
    asm volatile(
        "mma.sync.aligned.m16n8k16.row.col.f32.bf16.bf16.f32 "
        "{%0,%1,%2,%3}, {%4,%5,%6,%7}, {%8,%9}, {%0,%1,%2,%3};\n"
        : "+f"(c[0]), "+f"(c[1]), "+f"(c[2]), "+f"(c[3])
        : "r"(a[0]), "r"(a[1]), "r"(a[2]), "r"(a[3]), "r"(b[0]), "r"(b[1]));
}

__device__ __forceinline__ void store2(float* p, float2 v) { *(float2*)p = v; }
__device__ __forceinline__ void store2(__nv_bfloat16* p, float2 v)
{ *(__nv_bfloat162*)p = __floats2bfloat162_rn(v.x, v.y); }

// ---------------------------------------------------------------------------
// bf16 tensor-core NT GEMM, BM=128, BN=256, BK=32, 512 threads (16 warps 4x4),
// warp tile 32x64, cp.async 2-stage, dynamic smem (61.4 KB).
// ---------------------------------------------------------------------------
#define SK 40
#define GEMM_SMEM ((2 * 128 * SK + 2 * 256 * SK) * 2)   // bytes

template<bool RES, typename OUT>
__global__ void __launch_bounds__(512, 1)
gemm_bf16_kernel(const __nv_bfloat16* __restrict__ A,
                 const __nv_bfloat16* __restrict__ Bw,
                 const float* __restrict__ Res, OUT* __restrict__ C,
                 int N, int K)
{
    extern __shared__ __nv_bfloat16 smem[];
    __nv_bfloat16* As = smem;                    // 2 x 128*SK
    __nv_bfloat16* Bs = smem + 2 * 128 * SK;     // 2 x 256*SK

    const int m0 = blockIdx.y * 128, n0 = blockIdx.x * 256;
    const int tid  = threadIdx.x;
    const int warp = tid >> 5, lane = tid & 31;
    const int wm = warp >> 2, wn = warp & 3;     // 4 x 4 warp grid
    const int r  = lane >> 2;
    const int cc = (lane & 3) * 2;

    const int arow = tid >> 2, c8 = (tid & 3) * 8;   // A: 1 chunk/thread
    const int brow1 = 128 + arow;                     // B: 2 chunks/thread

    float acc[2][8][4];
#pragma unroll
    for (int i = 0; i < 2; i++)
#pragma unroll
        for (int j = 0; j < 8; j++)
#pragma unroll
            for (int q = 0; q < 4; q++) acc[i][j][q] = 0.f;

    const int niter = K / 32;

    // prologue: stage 0
    cpasync16(&As[arow * SK + c8],  &A [(size_t)(m0 + arow) * K + c8]);
    cpasync16(&Bs[arow * SK + c8],  &Bw[(size_t)(n0 + arow) * K + c8]);
    cpasync16(&Bs[brow1 * SK + c8], &Bw[(size_t)(n0 + brow1) * K + c8]);
    cp_commit();

    for (int i = 0; i < niter; i++) {
        cp_wait<0>();
        __syncthreads();

        if (i + 1 < niter) {
            int ko = (i + 1) * 32;
            __nv_bfloat16* Ad = As + ((i + 1) & 1) * 128 * SK;
            __nv_bfloat16* Bd = Bs + ((i + 1) & 1) * 256 * SK;
            cpasync16(&Ad[arow * SK + c8],  &A [(size_t)(m0 + arow) * K + ko + c8]);
            cpasync16(&Bd[arow * SK + c8],  &Bw[(size_t)(n0 + arow) * K + ko + c8]);
            cpasync16(&Bd[brow1 * SK + c8], &Bw[(size_t)(n0 + brow1) * K + ko + c8]);
            cp_commit();
        }

        const __nv_bfloat16* Ac = As + (i & 1) * 128 * SK;
        const __nv_bfloat16* Bc = Bs + (i & 1) * 256 * SK;
#pragma unroll
        for (int ks = 0; ks < 32; ks += 16) {
            unsigned afr[2][4], bfr[8][2];
#pragma unroll
            for (int mi = 0; mi < 2; mi++) {
                int mb = wm * 32 + mi * 16;
                afr[mi][0] = *(const unsigned*)&Ac[(mb + r    ) * SK + ks + cc    ];
                afr[mi][1] = *(const unsigned*)&Ac[(mb + r + 8) * SK + ks + cc    ];
                afr[mi][2] = *(const unsigned*)&Ac[(mb + r    ) * SK + ks + cc + 8];
                afr[mi][3] = *(const unsigned*)&Ac[(mb + r + 8) * SK + ks + cc + 8];
            }
#pragma unroll
            for (int ni = 0; ni < 8; ni++) {
                int nb = wn * 64 + ni * 8 + r;
                bfr[ni][0] = *(const unsigned*)&Bc[nb * SK + ks + cc    ];
                bfr[ni][1] = *(const unsigned*)&Bc[nb * SK + ks + cc + 8];
            }
#pragma unroll
            for (int mi = 0; mi < 2; mi++)
#pragma unroll
                for (int ni = 0; ni < 8; ni++)
                    mma16816(acc[mi][ni], afr[mi], bfr[ni]);
        }
    }

#pragma unroll
    for (int mi = 0; mi < 2; mi++) {
#pragma unroll
        for (int ni = 0; ni < 8; ni++) {
            int col = n0 + wn * 64 + ni * 8 + cc;
            size_t i0 = (size_t)(m0 + wm * 32 + mi * 16 + r    ) * N + col;
            size_t i1 = (size_t)(m0 + wm * 32 + mi * 16 + r + 8) * N + col;
            float2 v0 = make_float2(acc[mi][ni][0], acc[mi][ni][1]);
            float2 v1 = make_float2(acc[mi][ni][2], acc[mi][ni][3]);
            if (RES) {
                float2 r0 = *(const float2*)&Res[i0];
                float2 r1 = *(const float2*)&Res[i1];
                v0.x += r0.x; v0.y += r0.y; v1.x += r1.x; v1.y += r1.y;
            }
            store2(&C[i0], v0);
            store2(&C[i1], v1);
        }
    }
}

// ---------------------------------------------------------------------------
// Tensor-core flash attention: 64-query blocks, 4 warps, 64-key tiles,
// cp.async double-buffered K/V, log2-domain online softmax (exp2f).
// 1D grid ordered so the longest (high-qt) blocks launch first.
// ---------------------------------------------------------------------------
#define VS 72

__global__ void __launch_bounds__(128)
flash_mma_kernel(const __nv_bfloat16* __restrict__ qkv,
                 __nv_bfloat16* __restrict__ out)
{
    const int bi = blockIdx.x;
    const int qt = 31 - (bi >> 5);          // 32 q-tiles, big first
    const int h  = bi & 15;
    const int b  = (bi >> 4) & 1;

    __shared__ __nv_bfloat16 Ks [2][64 * VS];
    __shared__ __nv_bfloat16 Vsm[2][64 * VS];

    const int tid = threadIdx.x, warp = tid >> 5, lane = tid & 31;
    const int r = lane >> 2, cc = (lane & 3) * 2;
    const size_t rs = 3 * DD;
    const int qcol = h * HD;
    const int qrow0 = qt * 64 + warp * 16;

    // Q A-fragments straight from global
    unsigned qa[4][4];
    const __nv_bfloat16* qb = qkv + (size_t)(b * TT + qrow0) * rs + qcol;
#pragma unroll
    for (int ks = 0; ks < 4; ks++) {
        qa[ks][0] = *(const unsigned*)(qb + (size_t)(r    ) * rs + ks * 16 + cc    );
        qa[ks][1] = *(const unsigned*)(qb + (size_t)(r + 8) * rs + ks * 16 + cc    );
        qa[ks][2] = *(const unsigned*)(qb + (size_t)(r    ) * rs + ks * 16 + cc + 8);
        qa[ks][3] = *(const unsigned*)(qb + (size_t)(r + 8) * rs + ks * 16 + cc + 8);
    }

    float o[8][4];
#pragma unroll
    for (int i = 0; i < 8; i++)
#pragma unroll
        for (int q = 0; q < 4; q++) o[i][q] = 0.f;
    float m0 = -INFINITY, m1 = -INFINITY, l0 = 0.f, l1 = 0.f;

    // scale * log2(e): softmax computed in log2 domain -> single EX2 per element
    const float sl2 = 0.125f * 1.44269504088896f;
    const int row0 = qrow0 + r, row1 = qrow0 + r + 8;

    // ---- prologue: async-load tile 0 ----
    {
        const size_t kbase = (size_t)(b * TT) * rs + DD + qcol;
#pragma unroll
        for (int i = 0; i < 4; i++) {
            int idx = tid + i * 128;
            int row = idx >> 3, c8 = (idx & 7) * 8;
            size_t src = kbase + (size_t)row * rs + c8;
            cpasync16(&Ks [0][row * VS + c8], &qkv[src]);
            cpasync16(&Vsm[0][row * VS + c8], &qkv[src + DD]);
        }
        cp_commit();
    }

    for (int kt = 0; kt <= qt; kt++) {
        cp_wait<0>();
        __syncthreads();

        if (kt < qt) {
            int st = (kt + 1) & 1;
            const size_t kbase = (size_t)(b * TT + (kt + 1) * 64) * rs + DD + qcol;
#pragma unroll
            for (int i = 0; i < 4; i++) {
                int idx = tid + i * 128;
                int row = idx >> 3, c8 = (idx & 7) * 8;
                size_t src = kbase + (size_t)row * rs + c8;
                cpasync16(&Ks [st][row * VS + c8], &qkv[src]);
                cpasync16(&Vsm[st][row * VS + c8], &qkv[src + DD]);
            }
            cp_commit();
        }

        const __nv_bfloat16* Kc = Ks [kt & 1];
        const __nv_bfloat16* Vc = Vsm[kt & 1];

        // ---- S = Q K^T (16 x 64 per warp) ----
        float s[8][4];
#pragma unroll
        for (int i = 0; i < 8; i++)
#pragma unroll
            for (int q = 0; q < 4; q++) s[i][q] = 0.f;
#pragma unroll
        for (int ni = 0; ni < 8; ni++) {
#pragma unroll
            for (int ks = 0; ks < 4; ks++) {
                unsigned kb[2];
                kb[0] = *(const unsigned*)&Kc[(ni * 8 + r) * VS + ks * 16 + cc    ];
                kb[1] = *(const unsigned*)&Kc[(ni * 8 + r) * VS + ks * 16 + cc + 8];
                mma16816(s[ni], qa[ks], kb);
            }
        }

        // ---- log2-scale + causal mask (diagonal tile only) ----
        if (kt == qt) {
#pragma unroll
            for (int ni = 0; ni < 8; ni++) {
                int c0 = kt * 64 + ni * 8 + cc, c1 = c0 + 1;
                s[ni][0] = (c0 <= row0) ? s[ni][0] * sl2 : -INFINITY;
                s[ni][1] = (c1 <= row0) ? s[ni][1] * sl2 : -INFINITY;
                s[ni][2] = (c0 <= row1) ? s[ni][2] * sl2 : -INFINITY;
                s[ni][3] = (c1 <= row1) ? s[ni][3] * sl2 : -INFINITY;
            }
        } else {
#pragma unroll
            for (int ni = 0; ni < 8; ni++)
#pragma unroll
                for (int q = 0; q < 4; q++) s[ni][q] *= sl2;
        }

        // ---- online softmax (log2 domain) ----
        float mx0 = -INFINITY, mx1 = -INFINITY;
#pragma unroll
        for (int ni = 0; ni < 8; ni++) {
            mx0 = fmaxf(mx0, fmaxf(s[ni][0], s[ni][1]));
            mx1 = fmaxf(mx1, fmaxf(s[ni][2], s[ni][3]));
        }
        mx0 = fmaxf(mx0, __shfl_xor_sync(0xffffffffu, mx0, 1));
        mx0 = fmaxf(mx0, __shfl_xor_sync(0xffffffffu, mx0, 2));
        mx1 = fmaxf(mx1, __shfl_xor_sync(0xffffffffu, mx1, 1));
        mx1 = fmaxf(mx1, __shfl_xor_sync(0xffffffffu, mx1, 2));

        float mn0 = fmaxf(m0, mx0), mn1 = fmaxf(m1, mx1);
        float a0 = exp2f(m0 - mn0), a1 = exp2f(m1 - mn1);
        m0 = mn0; m1 = mn1;

        float ls0 = 0.f, ls1 = 0.f;
#pragma unroll
        for (int ni = 0; ni < 8; ni++) {
            s[ni][0] = exp2f(s[ni][0] - mn0);
            s[ni][1] = exp2f(s[ni][1] - mn0);
            s[ni][2] = exp2f(s[ni][2] - mn1);
            s[ni][3] = exp2f(s[ni][3] - mn1);
            ls0 += s[ni][0] + s[ni][1];
            ls1 += s[ni][2] + s[ni][3];
        }
        ls0 += __shfl_xor_sync(0xffffffffu, ls0, 1);
        ls0 += __shfl_xor_sync(0xffffffffu, ls0, 2);
        ls1 += __shfl_xor_sync(0xffffffffu, ls1, 1);
        ls1 += __shfl_xor_sync(0xffffffffu, ls1, 2);
        l0 = l0 * a0 + ls0;
        l1 = l1 * a1 + ls1;

#pragma unroll
        for (int ni = 0; ni < 8; ni++) {
            o[ni][0] *= a0; o[ni][1] *= a0;
            o[ni][2] *= a1; o[ni][3] *= a1;
        }

        // ---- O += P V ----
#pragma unroll
        for (int ks2 = 0; ks2 < 4; ks2++) {
            unsigned pa[4];
            pa[0] = ((unsigned)__bfloat16_as_ushort(__float2bfloat16(s[2*ks2  ][1])) << 16)
                  |  (unsigned)__bfloat16_as_ushort(__float2bfloat16(s[2*ks2  ][0]));
            pa[1] = ((unsigned)__bfloat16_as_ushort(__float2bfloat16(s[2*ks2  ][3])) << 16)
                  |  (unsigned)__bfloat16_as_ushort(__float2bfloat16(s[2*ks2  ][2]));
            pa[2] = ((unsigned)__bfloat16_as_ushort(__float2bfloat16(s[2*ks2+1][1])) << 16)
                  |  (unsigned)__bfloat16_as_ushort(__float2bfloat16(s[2*ks2+1][0]));
            pa[3] = ((unsigned)__bfloat16_as_ushort(__float2bfloat16(s[2*ks2+1][3])) << 16)
                  |  (unsigned)__bfloat16_as_ushort(__float2bfloat16(s[2*ks2+1][2]));

#pragma unroll
            for (int njp = 0; njp < 4; njp++) {
                const __nv_bfloat16* vp =
                    &Vc[(ks2 * 16 + (lane & 15)) * VS + njp * 16 + ((lane >> 4) * 8)];
                unsigned addr = (unsigned)__cvta_generic_to_shared(vp);
                unsigned t0, t1, t2, t3;
                asm volatile(
                    "ldmatrix.sync.aligned.m8n8.x4.trans.shared.b16 "
                    "{%0,%1,%2,%3}, [%4];"
                    : "=r"(t0), "=r"(t1), "=r"(t2), "=r"(t3) : "r"(addr));
                unsigned vb0[2] = {t0, t1}, vb1[2] = {t2, t3};
                mma16816(o[2*njp    ], pa, vb0);
                mma16816(o[2*njp + 1], pa, vb1);
            }
        }
    }

    float inv0 = 1.0f / l0, inv1 = 1.0f / l1;
#pragma unroll
    for (int ni = 0; ni < 8; ni++) {
        size_t i0 = (size_t)(b * TT + row0) * DD + qcol + ni * 8 + cc;
        size_t i1 = (size_t)(b * TT + row1) * DD + qcol + ni * 8 + cc;
        *(__nv_bfloat162*)&out[i0] = __floats2bfloat162_rn(o[ni][0] * inv0, o[ni][1] * inv0);
        *(__nv_bfloat162*)&out[i1] = __floats2bfloat162_rn(o[ni][2] * inv1, o[ni][3] * inv1);
    }
}

// ---------------------------------------------------------------------------
// Fused rmsnorm2 + rotation FFN + SiLU + final residual combine.
// ---------------------------------------------------------------------------
__global__ void __launch_bounds__(256)
rmsrot_kernel(const float* __restrict__ x1, const float* __restrict__ w,
              const float* __restrict__ gamma, const float* __restrict__ beta,
              const float* __restrict__ angles, const float* __restrict__ gate,
              const float* __restrict__ bias, const int* __restrict__ pi,
              const int* __restrict__ pj, float* __restrict__ out)
{
    int m = blockIdx.x;
    int tid = threadIdx.x;
    __shared__ float sr[DD];
    __shared__ float red[8];

    const float* xr = x1 + (size_t)m * DD;
    float v[4];
    float s = 0.f;
#pragma unroll
    for (int u = 0; u < 4; u++) {
        v[u] = xr[tid + u * 256];
        s += v[u] * v[u];
    }
#pragma unroll
    for (int off = 16; off; off >>= 1) s += __shfl_xor_sync(0xffffffffu, s, off);
    int lane = tid & 31, wid = tid >> 5;
    if (lane == 0) red[wid] = s;
    __syncthreads();
    if (tid < 32) {
        float t = (tid < 8) ? red[tid] : 0.f;
#pragma unroll
        for (int off = 4; off; off >>= 1) t += __shfl_xor_sync(0xffffffffu, t, off);
        if (tid == 0) red[0] = t;
    }
    __syncthreads();
    float rms = rsqrtf(red[0] * (1.0f / (float)DD) + 1.1920929e-07f);

    float h2r[4];
#pragma unroll
    for (int u = 0; u < 4; u++) {
        int d = tid + u * 256;
        h2r[u] = v[u] * rms * w[d] * gamma[d] + beta[d];
        sr[d] = h2r[u];
    }
    __syncthreads();

#pragma unroll
    for (int p = 0; p < NP; p++) {
        int ii = pi[p * PP + tid];
        int jj = pj[p * PP + tid];
        float a  = angles[p * PP + tid];
        float ca = cosf(a), sa = sinf(a);
        float hi = sr[ii], hj = sr[jj];
        sr[ii] = hi * ca - hj * sa;
        sr[jj] = hi * sa + hj * ca;
        __syncthreads();
#pragma unroll
        for (int u = 0; u < 4; u++) {
            int d = tid + u * 256;
            float t = sr[d] * gate[p * DD + d] + bias[p * DD + d];
            sr[d] = t / (1.f + __expf(-t));
        }
        __syncthreads();
    }

#pragma unroll
    for (int u = 0; u < 4; u++) {
        int d = tid + u * 256;
        out[(size_t)m * DD + d] = v[u] + sr[d] - h2r[u];
    }
}

// ---------------------------------------------------------------------------
// Launch
// ---------------------------------------------------------------------------
extern "C" void kernel_launch(void* const* d_in, const int* in_sizes, int n_in,
                              void* d_out, int out_size)
{
    const float* x      = (const float*)d_in[0];
    const float* gamma  = (const float*)d_in[1];
    const float* beta   = (const float*)d_in[2];
    const float* qkv_w  = (const float*)d_in[3];
    const float* o_w    = (const float*)d_in[4];
    const float* n1w    = (const float*)d_in[5];
    const float* n2w    = (const float*)d_in[6];
    const float* angles = (const float*)d_in[7];
    const float* gate   = (const float*)d_in[8];
    const float* bias   = (const float*)d_in[9];
    const int*   pi     = (const int*)d_in[10];
    const int*   pj     = (const int*)d_in[11];
    float* out = (float*)d_out;

    __nv_bfloat16 *hb, *wb, *qkvb, *attnb;
    float *x1;
    cudaGetSymbolAddress((void**)&hb,    g_hb);
    cudaGetSymbolAddress((void**)&wb,    g_wb);
    cudaGetSymbolAddress((void**)&qkvb,  g_qkvb);
    cudaGetSymbolAddress((void**)&attnb, g_attnb);
    cudaGetSymbolAddress((void**)&x1,    g_x1);

    static bool attr_set = false;
    if (!attr_set) {
        cudaFuncSetAttribute(gemm_bf16_kernel<false, __nv_bfloat16>,
                             cudaFuncAttributeMaxDynamicSharedMemorySize, GEMM_SMEM);
        cudaFuncSetAttribute(gemm_bf16_kernel<true, float>,
                             cudaFuncAttributeMaxDynamicSharedMemorySize, GEMM_SMEM);
        attr_set = true;
    }

    // 0+1. fused weight conversion + rmsnorm1
    prep_kernel<<<BT + 4096, 256>>>(x, n1w, gamma, beta, hb, qkv_w, o_w, wb);

    // 2. qkv = h @ qkv_w.T  -> bf16  [4096, 3072]
    gemm_bf16_kernel<false, __nv_bfloat16>
        <<<dim3(3 * DD / 256, BT / 128), 512, GEMM_SMEM>>>(
        hb, wb, nullptr, qkvb, 3 * DD, DD);

    // 3. causal attention (tensor core, 64-q blocks, async pipeline)
    flash_mma_kernel<<<1024, 128>>>(qkvb, attnb);

    // 4. x1 = x + attn @ o_w.T
    gemm_bf16_kernel<true, float>
        <<<dim3(DD / 256, BT / 128), 512, GEMM_SMEM>>>(
        attnb, wb + (size_t)3 * DD * DD, x, x1, DD, DD);

    // 5+6. fused rmsnorm2 + rotations + silu + residual -> out
    rmsrot_kernel<<<BT, 256>>>(x1, n2w, gamma, beta, angles, gate, bias, pi, pj, out);
}